// round 5
// baseline (speedup 1.0000x reference)
#include <cuda_runtime.h>
#include <math.h>
#include <stdint.h>

// Problem dims
#define Bv    2
#define NQv   1024
#define NKVv  2048
#define Dv    1024
#define Hv    16
#define DHv   64
#define Ev    8
#define FFv   4096
#define TQ    (Bv*NQv)
#define TKV   (Bv*NKVv)
#define MAXTOK 2048

// ---------------- scratch ----------------
__device__ float g_x[TQ*Dv];
__device__ float g_ln1[TQ*Dv];
__device__ float g_lnkv[TKV*Dv];
__device__ float g_qp[TQ*Dv];
__device__ float g_kvp[TKV*2048];
__device__ float g_scores[(size_t)Bv*Hv*NQv*NKVv];
__device__ float g_ao[TQ*Dv];
__device__ float g_h[(size_t)TQ*2*FFv];
__device__ float g_eo[(size_t)TQ*2*Dv];
__device__ float g_probs[TQ*2];
__device__ int   g_counts[Ev];
__device__ int   g_elist[Ev*MAXTOK];

// ---------------- layernorm ----------------
__global__ void ln_k(const float* __restrict__ x, float* __restrict__ y,
                     const float* __restrict__ g, const float* __restrict__ b) {
    long row = blockIdx.x;
    const float* xr = x + row * 1024;
    float* yr = y + row * 1024;
    __shared__ float sm[1024];
    __shared__ float red[256];
    int tid = threadIdx.x;
    float s = 0.f;
    #pragma unroll
    for (int i = 0; i < 4; i++) { float v = xr[tid + (i<<8)]; sm[tid + (i<<8)] = v; s += v; }
    red[tid] = s; __syncthreads();
    for (int st = 128; st > 0; st >>= 1) { if (tid < st) red[tid] += red[tid + st]; __syncthreads(); }
    float mean = red[0] * (1.0f/1024.0f); __syncthreads();
    float s2 = 0.f;
    #pragma unroll
    for (int i = 0; i < 4; i++) { float d = sm[tid + (i<<8)] - mean; s2 += d*d; }
    red[tid] = s2; __syncthreads();
    for (int st = 128; st > 0; st >>= 1) { if (tid < st) red[tid] += red[tid + st]; __syncthreads(); }
    float var = red[0] * (1.0f/1024.0f);
    float rstd = rsqrtf(var + 1e-5f);
    #pragma unroll
    for (int i = 0; i < 4; i++) { int c = tid + (i<<8); yr[c] = (sm[c]-mean)*rstd*g[c] + b[c]; }
}

// ---------------- softmax ----------------
__global__ void softmax_k(float* __restrict__ S, int L) {
    float* r = S + (size_t)blockIdx.x * L;
    int tid = threadIdx.x;
    __shared__ float red[256];
    int cnt = L >> 8;
    float v[8];
    float mx = -3.4e38f;
    for (int i = 0; i < cnt; i++) { v[i] = r[tid + (i<<8)]; mx = fmaxf(mx, v[i]); }
    red[tid] = mx; __syncthreads();
    for (int st = 128; st > 0; st >>= 1) { if (tid < st) red[tid] = fmaxf(red[tid], red[tid+st]); __syncthreads(); }
    mx = red[0]; __syncthreads();
    float sum = 0.f;
    for (int i = 0; i < cnt; i++) { v[i] = expf(v[i]-mx); sum += v[i]; }
    red[tid] = sum; __syncthreads();
    for (int st = 128; st > 0; st >>= 1) { if (tid < st) red[tid] += red[tid+st]; __syncthreads(); }
    float inv = 1.0f / red[0];
    for (int i = 0; i < cnt; i++) r[tid + (i<<8)] = v[i]*inv;
}

// ---------------- tf32 mma helpers ----------------
__device__ __forceinline__ unsigned f2tf(float x) {
    unsigned r; asm("cvt.rna.tf32.f32 %0, %1;" : "=r"(r) : "f"(x)); return r;
}
__device__ __forceinline__ void split_store(unsigned* h, unsigned* l, int idx, float x) {
    unsigned hh = f2tf(x);
    h[idx] = hh;
    l[idx] = f2tf(x - __uint_as_float(hh));
}
__device__ __forceinline__ void mma8(float* c, const unsigned* a, const unsigned* b) {
    asm volatile("mma.sync.aligned.m16n8k8.row.col.f32.tf32.tf32.f32 "
        "{%0,%1,%2,%3},{%4,%5,%6,%7},{%8,%9},{%0,%1,%2,%3};"
        : "+f"(c[0]), "+f"(c[1]), "+f"(c[2]), "+f"(c[3])
        : "r"(a[0]), "r"(a[1]), "r"(a[2]), "r"(a[3]), "r"(b[0]), "r"(b[1]));
}

// ---------------- 3xTF32 GEMM: split at staging, pipelined loads ----------------
// C[M,N] = alpha * A[M,K] * op(B) + bias + res
// BT=true : B is [N,K] row-major;  BT=false: B is [K,N] row-major
template<bool BT>
__global__ __launch_bounds__(256, 2) void mma_gemm(
    const float* __restrict__ A, int lda, long long sAo, long long sAi,
    const float* __restrict__ B, int ldb, long long sBo, long long sBi,
    float* __restrict__ C, int ldc, long long sCo, long long sCi,
    int M, int N, int K, int inner,
    const float* __restrict__ bias, float alpha, const float* __restrict__ res)
{
    int z = blockIdx.z;
    int zo = z / inner, zi = z - zo * inner;
    A += zo * sAo + zi * sAi;
    B += zo * sBo + zi * sBi;
    C += zo * sCo + zi * sCi;
    if (res) res += zo * sCo + zi * sCi;

    __shared__ unsigned As_h[2560], As_l[2560];   // [m][k] stride 20
    __shared__ unsigned Bs_h[1280], Bs_l[1280];   // BT: [n][k] s20 ; !BT: [k][n] s72

    int tid = threadIdx.x, lane = tid & 31, warp = tid >> 5;
    int g = lane >> 2, tig = lane & 3;
    int wm = (warp & 3) * 32, wn = (warp >> 2) * 32;
    int m0 = blockIdx.y * 128, n0 = blockIdx.x * 64;

    float c[2][4][4] = {};
    float4 aR[2], bR;

    // per-thread staging coords
    int ar0 = tid >> 2,        akq = (tid & 3) << 2;          // A: rows tid/4, tid/4+64
    int bn, bkq, bkk, bnq;
    if (BT) { bn = tid >> 2; bkq = (tid & 3) << 2; bkk = 0; bnq = 0; }
    else    { bkk = tid >> 4; bnq = (tid & 15) << 2; bn = 0; bkq = 0; }

    // prologue: load tile 0
    {
        int gm0 = m0 + ar0, gm1 = m0 + ar0 + 64;
        aR[0] = (gm0 < M) ? *(const float4*)&A[(long long)gm0 * lda + akq] : make_float4(0,0,0,0);
        aR[1] = (gm1 < M) ? *(const float4*)&A[(long long)gm1 * lda + akq] : make_float4(0,0,0,0);
        if (BT) bR = *(const float4*)&B[(long long)(n0 + bn) * ldb + bkq];
        else    bR = *(const float4*)&B[(long long)bkk * ldb + n0 + bnq];
    }

    for (int k0 = 0; k0 < K; k0 += 16) {
        // stage regs -> smem with split
        {
            int base0 = ar0*20 + akq, base1 = (ar0+64)*20 + akq;
            split_store(As_h, As_l, base0,   aR[0].x);
            split_store(As_h, As_l, base0+1, aR[0].y);
            split_store(As_h, As_l, base0+2, aR[0].z);
            split_store(As_h, As_l, base0+3, aR[0].w);
            split_store(As_h, As_l, base1,   aR[1].x);
            split_store(As_h, As_l, base1+1, aR[1].y);
            split_store(As_h, As_l, base1+2, aR[1].z);
            split_store(As_h, As_l, base1+3, aR[1].w);
            int bb = BT ? (bn*20 + bkq) : (bkk*72 + bnq);
            split_store(Bs_h, Bs_l, bb,   bR.x);
            split_store(Bs_h, Bs_l, bb+1, bR.y);
            split_store(Bs_h, Bs_l, bb+2, bR.z);
            split_store(Bs_h, Bs_l, bb+3, bR.w);
        }
        __syncthreads();

        // prefetch next tile (overlaps with MMA below)
        int k1 = k0 + 16;
        if (k1 < K) {
            int gm0 = m0 + ar0, gm1 = m0 + ar0 + 64;
            aR[0] = (gm0 < M) ? *(const float4*)&A[(long long)gm0 * lda + k1 + akq] : make_float4(0,0,0,0);
            aR[1] = (gm1 < M) ? *(const float4*)&A[(long long)gm1 * lda + k1 + akq] : make_float4(0,0,0,0);
            if (BT) bR = *(const float4*)&B[(long long)(n0 + bn) * ldb + k1 + bkq];
            else    bR = *(const float4*)&B[(long long)(k1 + bkk) * ldb + n0 + bnq];
        }

        #pragma unroll
        for (int kk = 0; kk < 16; kk += 8) {
            unsigned ah[2][4], al[2][4];
            #pragma unroll
            for (int mt = 0; mt < 2; mt++) {
                int rb = wm + mt*16 + g;
                int i0 = rb*20 + kk + tig, i1 = (rb+8)*20 + kk + tig;
                ah[mt][0] = As_h[i0];   al[mt][0] = As_l[i0];
                ah[mt][1] = As_h[i1];   al[mt][1] = As_l[i1];
                ah[mt][2] = As_h[i0+4]; al[mt][2] = As_l[i0+4];
                ah[mt][3] = As_h[i1+4]; al[mt][3] = As_l[i1+4];
            }
            unsigned bh[4][2], bl[4][2];
            #pragma unroll
            for (int nt = 0; nt < 4; nt++) {
                int nb = wn + nt*8 + g;
                int j0, j1;
                if (BT) { j0 = nb*20 + kk + tig;  j1 = j0 + 4; }
                else    { j0 = (kk+tig)*72 + nb;  j1 = (kk+tig+4)*72 + nb; }
                bh[nt][0] = Bs_h[j0]; bl[nt][0] = Bs_l[j0];
                bh[nt][1] = Bs_h[j1]; bl[nt][1] = Bs_l[j1];
            }
            #pragma unroll
            for (int mt = 0; mt < 2; mt++)
                #pragma unroll
                for (int nt = 0; nt < 4; nt++) {
                    mma8(c[mt][nt], ah[mt], bh[nt]);
                    mma8(c[mt][nt], ah[mt], bl[nt]);
                    mma8(c[mt][nt], al[mt], bh[nt]);
                }
        }
        __syncthreads();
    }

    // ---- epilogue ----
    #pragma unroll
    for (int mt = 0; mt < 2; mt++) {
        int r0 = m0 + wm + mt*16 + g;
        #pragma unroll
        for (int nt = 0; nt < 4; nt++) {
            int col = n0 + wn + nt*8 + tig*2;
            float bv0 = bias ? bias[col]   : 0.f;
            float bv1 = bias ? bias[col+1] : 0.f;
            if (r0 < M) {
                float v0 = alpha*c[mt][nt][0] + bv0;
                float v1 = alpha*c[mt][nt][1] + bv1;
                if (res) { v0 += res[(long long)r0*ldc + col]; v1 += res[(long long)r0*ldc + col + 1]; }
                C[(long long)r0*ldc + col]     = v0;
                C[(long long)r0*ldc + col + 1] = v1;
            }
            int r1 = r0 + 8;
            if (r1 < M) {
                float v2 = alpha*c[mt][nt][2] + bv0;
                float v3 = alpha*c[mt][nt][3] + bv1;
                if (res) { v2 += res[(long long)r1*ldc + col]; v3 += res[(long long)r1*ldc + col + 1]; }
                C[(long long)r1*ldc + col]     = v2;
                C[(long long)r1*ldc + col + 1] = v3;
            }
        }
    }
}

// ---------------- JAX threefry2x32 / normal ----------------
__device__ __forceinline__ void threefry42(unsigned c0, unsigned c1, unsigned& o0, unsigned& o1) {
    const unsigned k0 = 0u, k1 = 42u;
    const unsigned k2 = 0x1BD11BDAu ^ k0 ^ k1;
    unsigned x0 = c0 + k0, x1 = c1 + k1;
#define TF_R(r) { x0 += x1; x1 = (x1 << r) | (x1 >> (32 - r)); x1 ^= x0; }
    TF_R(13) TF_R(15) TF_R(26) TF_R(6)   x0 += k1; x1 += k2 + 1u;
    TF_R(17) TF_R(29) TF_R(16) TF_R(24)  x0 += k2; x1 += k0 + 2u;
    TF_R(13) TF_R(15) TF_R(26) TF_R(6)   x0 += k0; x1 += k1 + 3u;
    TF_R(17) TF_R(29) TF_R(16) TF_R(24)  x0 += k1; x1 += k2 + 4u;
    TF_R(13) TF_R(15) TF_R(26) TF_R(6)   x0 += k2; x1 += k0 + 5u;
#undef TF_R
    o0 = x0; o1 = x1;
}

__device__ __forceinline__ float erfinv_f(float x) {
    float w = -log1pf(__fmul_rn(-x, x));
    float p;
    if (w < 5.0f) {
        w = __fadd_rn(w, -2.5f);
        p = 2.81022636e-08f;
        p = __fadd_rn(__fmul_rn(p, w),  3.43273939e-07f);
        p = __fadd_rn(__fmul_rn(p, w), -3.5233877e-06f);
        p = __fadd_rn(__fmul_rn(p, w), -4.39150654e-06f);
        p = __fadd_rn(__fmul_rn(p, w),  0.00021858087f);
        p = __fadd_rn(__fmul_rn(p, w), -0.00125372503f);
        p = __fadd_rn(__fmul_rn(p, w), -0.00417768164f);
        p = __fadd_rn(__fmul_rn(p, w),  0.246640727f);
        p = __fadd_rn(__fmul_rn(p, w),  1.50140941f);
    } else {
        w = __fadd_rn(sqrtf(w), -3.0f);
        p = -0.000200214257f;
        p = __fadd_rn(__fmul_rn(p, w),  0.000100950558f);
        p = __fadd_rn(__fmul_rn(p, w),  0.00134934322f);
        p = __fadd_rn(__fmul_rn(p, w), -0.00367342844f);
        p = __fadd_rn(__fmul_rn(p, w),  0.00573950773f);
        p = __fadd_rn(__fmul_rn(p, w), -0.0076224613f);
        p = __fadd_rn(__fmul_rn(p, w),  0.00943887047f);
        p = __fadd_rn(__fmul_rn(p, w),  1.00167406f);
        p = __fadd_rn(__fmul_rn(p, w),  2.83297682f);
    }
    return __fmul_rn(p, x);
}

// partitionable threefry: counter (0, i), bits = out0 ^ out1
__device__ __forceinline__ float jax_normal(int i) {
    unsigned o0, o1;
    threefry42(0u, (unsigned)i, o0, o1);
    unsigned bits = o0 ^ o1;
    unsigned fb = (bits >> 9) | 0x3f800000u;
    float u01 = __fadd_rn(__uint_as_float(fb), -1.0f);
    const float lo = -0.99999994f;
    float u = __fadd_rn(__fmul_rn(u01, 2.0f), lo);
    u = fmaxf(lo, u);
    return __fmul_rn(1.41421354f, erfinv_f(u));
}

// ---------------- MoE router ----------------
__global__ void zero_counts_k() { if (threadIdx.x < Ev) g_counts[threadIdx.x] = 0; }

__global__ void router_k(const float* __restrict__ xm,
                         const float* __restrict__ rw, const float* __restrict__ rb,
                         const float* __restrict__ nw, const float* __restrict__ nb) {
    int t = blockIdx.x;
    int tid = threadIdx.x;
    int w = tid >> 5, lane = tid & 31;
    __shared__ float sl[8], sn[8];
    const float* xr = xm + (long long)t * 1024;
    const float* rwe = rw + w * 1024;
    const float* nwe = nw + w * 1024;
    float sr = 0.f, s_n = 0.f;
    for (int d = lane; d < 1024; d += 32) {
        float xv = xr[d];
        sr  += xv * rwe[d];
        s_n += xv * nwe[d];
    }
    #pragma unroll
    for (int o = 16; o; o >>= 1) {
        sr  += __shfl_down_sync(0xffffffffu, sr, o);
        s_n += __shfl_down_sync(0xffffffffu, s_n, o);
    }
    if (lane == 0) { sl[w] = sr + rb[w]; sn[w] = s_n + nb[w]; }
    __syncthreads();
    if (tid == 0) {
        float noisy[8];
        #pragma unroll
        for (int e = 0; e < 8; e++) {
            float nrm = jax_normal(t * 8 + e);
            float zz = sn[e];
            float sp = fmaxf(zz, 0.f) + log1pf(expf(-fabsf(zz)));
            noisy[e] = sl[e] + nrm * sp;
        }
        int i1 = 0;
        #pragma unroll
        for (int e = 1; e < 8; e++) if (noisy[e] > noisy[i1]) i1 = e;
        int i2 = (i1 == 0) ? 1 : 0;
        #pragma unroll
        for (int e = 0; e < 8; e++) if (e != i1 && noisy[e] > noisy[i2]) i2 = e;
        float mx = noisy[i1];
        float e1 = expf(noisy[i1] - mx);
        float e2 = expf(noisy[i2] - mx);
        float Z  = e1 + e2;
        g_probs[2*t]   = e1 / Z;
        g_probs[2*t+1] = e2 / Z;
        int p1 = atomicAdd(&g_counts[i1], 1); g_elist[i1 * MAXTOK + p1] = 2*t;
        int p2 = atomicAdd(&g_counts[i2], 1); g_elist[i2 * MAXTOK + p2] = 2*t + 1;
    }
}

// ---------------- MoE tensor-core GEMMs (split-at-stage + pipeline) ----------------
__global__ __launch_bounds__(256, 2) void moe_mma1(const float* __restrict__ xm,
                                                   const float* __restrict__ w1,
                                                   const float* __restrict__ b1) {
    int e = blockIdx.z;
    int cnt = g_counts[e];
    int m0 = blockIdx.y * 128;
    if (m0 >= cnt) return;
    int n0 = blockIdx.x * 64;

    __shared__ int slots[128];
    __shared__ unsigned As_h[2560], As_l[2560];
    __shared__ unsigned Bs_h[1280], Bs_l[1280];

    int tid = threadIdx.x, lane = tid & 31, warp = tid >> 5;
    int g = lane >> 2, tig = lane & 3;
    int wm = (warp & 3) * 32, wn = (warp >> 2) * 32;
    if (tid < 128) slots[tid] = (m0 + tid < cnt) ? g_elist[e * MAXTOK + m0 + tid] : -1;
    __syncthreads();

    const float* Be = w1 + (long long)e * 1024 * 4096;
    float c[2][4][4] = {};
    float4 aR[2], bR;

    int ar0 = tid >> 2, akq = (tid & 3) << 2;
    int bkk = tid >> 4, bnq = (tid & 15) << 2;
    int s0g = slots[ar0], s1g = slots[ar0 + 64];

    aR[0] = (s0g >= 0) ? *(const float4*)&xm[(long long)(s0g >> 1)*1024 + akq] : make_float4(0,0,0,0);
    aR[1] = (s1g >= 0) ? *(const float4*)&xm[(long long)(s1g >> 1)*1024 + akq] : make_float4(0,0,0,0);
    bR = *(const float4*)&Be[(long long)bkk * 4096 + n0 + bnq];

    for (int k0 = 0; k0 < 1024; k0 += 16) {
        {
            int base0 = ar0*20 + akq, base1 = (ar0+64)*20 + akq;
            split_store(As_h, As_l, base0,   aR[0].x);
            split_store(As_h, As_l, base0+1, aR[0].y);
            split_store(As_h, As_l, base0+2, aR[0].z);
            split_store(As_h, As_l, base0+3, aR[0].w);
            split_store(As_h, As_l, base1,   aR[1].x);
            split_store(As_h, As_l, base1+1, aR[1].y);
            split_store(As_h, As_l, base1+2, aR[1].z);
            split_store(As_h, As_l, base1+3, aR[1].w);
            int bb = bkk*72 + bnq;
            split_store(Bs_h, Bs_l, bb,   bR.x);
            split_store(Bs_h, Bs_l, bb+1, bR.y);
            split_store(Bs_h, Bs_l, bb+2, bR.z);
            split_store(Bs_h, Bs_l, bb+3, bR.w);
        }
        __syncthreads();
        int k1 = k0 + 16;
        if (k1 < 1024) {
            aR[0] = (s0g >= 0) ? *(const float4*)&xm[(long long)(s0g >> 1)*1024 + k1 + akq] : make_float4(0,0,0,0);
            aR[1] = (s1g >= 0) ? *(const float4*)&xm[(long long)(s1g >> 1)*1024 + k1 + akq] : make_float4(0,0,0,0);
            bR = *(const float4*)&Be[(long long)(k1 + bkk) * 4096 + n0 + bnq];
        }
        #pragma unroll
        for (int kk = 0; kk < 16; kk += 8) {
            unsigned ah[2][4], al[2][4];
            #pragma unroll
            for (int mt = 0; mt < 2; mt++) {
                int rb = wm + mt*16 + g;
                int i0 = rb*20 + kk + tig, i1 = (rb+8)*20 + kk + tig;
                ah[mt][0] = As_h[i0];   al[mt][0] = As_l[i0];
                ah[mt][1] = As_h[i1];   al[mt][1] = As_l[i1];
                ah[mt][2] = As_h[i0+4]; al[mt][2] = As_l[i0+4];
                ah[mt][3] = As_h[i1+4]; al[mt][3] = As_l[i1+4];
            }
            unsigned bh[4][2], bl[4][2];
            #pragma unroll
            for (int nt = 0; nt < 4; nt++) {
                int nb = wn + nt*8 + g;
                int j0 = (kk+tig)*72 + nb, j1 = (kk+tig+4)*72 + nb;
                bh[nt][0] = Bs_h[j0]; bl[nt][0] = Bs_l[j0];
                bh[nt][1] = Bs_h[j1]; bl[nt][1] = Bs_l[j1];
            }
            #pragma unroll
            for (int mt = 0; mt < 2; mt++)
                #pragma unroll
                for (int nt = 0; nt < 4; nt++) {
                    mma8(c[mt][nt], ah[mt], bh[nt]);
                    mma8(c[mt][nt], ah[mt], bl[nt]);
                    mma8(c[mt][nt], al[mt], bh[nt]);
                }
        }
        __syncthreads();
    }

    #pragma unroll
    for (int mt = 0; mt < 2; mt++) {
        int lr0 = wm + mt*16 + g;
        int s0 = slots[lr0], s1 = slots[lr0 + 8];
        #pragma unroll
        for (int nt = 0; nt < 4; nt++) {
            int col = n0 + wn + nt*8 + tig*2;
            float bv0 = b1[e*4096 + col], bv1 = b1[e*4096 + col + 1];
            if (s0 >= 0) {
                float v0 = c[mt][nt][0] + bv0;
                float v1 = c[mt][nt][1] + bv1;
                v0 = 0.5f * v0 * (1.0f + erff(v0 * 0.70710677f));
                v1 = 0.5f * v1 * (1.0f + erff(v1 * 0.70710677f));
                g_h[(long long)s0*4096 + col]     = v0;
                g_h[(long long)s0*4096 + col + 1] = v1;
            }
            if (s1 >= 0) {
                float v2 = c[mt][nt][2] + bv0;
                float v3 = c[mt][nt][3] + bv1;
                v2 = 0.5f * v2 * (1.0f + erff(v2 * 0.70710677f));
                v3 = 0.5f * v3 * (1.0f + erff(v3 * 0.70710677f));
                g_h[(long long)s1*4096 + col]     = v2;
                g_h[(long long)s1*4096 + col + 1] = v3;
            }
        }
    }
}

__global__ __launch_bounds__(256, 2) void moe_mma2(const float* __restrict__ w2,
                                                   const float* __restrict__ b2) {
    int e = blockIdx.z;
    int cnt = g_counts[e];
    int m0 = blockIdx.y * 128;
    if (m0 >= cnt) return;
    int n0 = blockIdx.x * 64;

    __shared__ int slots[128];
    __shared__ unsigned As_h[2560], As_l[2560];
    __shared__ unsigned Bs_h[1280], Bs_l[1280];

    int tid = threadIdx.x, lane = tid & 31, warp = tid >> 5;
    int g = lane >> 2, tig = lane & 3;
    int wm = (warp & 3) * 32, wn = (warp >> 2) * 32;
    if (tid < 128) slots[tid] = (m0 + tid < cnt) ? g_elist[e * MAXTOK + m0 + tid] : -1;
    __syncthreads();

    const float* Be = w2 + (long long)e * 4096 * 1024;
    float c[2][4][4] = {};
    float4 aR[2], bR;

    int ar0 = tid >> 2, akq = (tid & 3) << 2;
    int bkk = tid >> 4, bnq = (tid & 15) << 2;
    int s0g = slots[ar0], s1g = slots[ar0 + 64];

    aR[0] = (s0g >= 0) ? *(const float4*)&g_h[(long long)s0g*4096 + akq] : make_float4(0,0,0,0);
    aR[1] = (s1g >= 0) ? *(const float4*)&g_h[(long long)s1g*4096 + akq] : make_float4(0,0,0,0);
    bR = *(const float4*)&Be[(long long)bkk * 1024 + n0 + bnq];

    for (int k0 = 0; k0 < 4096; k0 += 16) {
        {
            int base0 = ar0*20 + akq, base1 = (ar0+64)*20 + akq;
            split_store(As_h, As_l, base0,   aR[0].x);
            split_store(As_h, As_l, base0+1, aR[0].y);
            split_store(As_h, As_l, base0+2, aR[0].z);
            split_store(As_h, As_l, base0+3, aR[0].w);
            split_store(As_h, As_l, base1,   aR[1].x);
            split_store(As_h, As_l, base1+1, aR[1].y);
            split_store(As_h, As_l, base1+2, aR[1].z);
            split_store(As_h, As_l, base1+3, aR[1].w);
            int bb = bkk*72 + bnq;
            split_store(Bs_h, Bs_l, bb,   bR.x);
            split_store(Bs_h, Bs_l, bb+1, bR.y);
            split_store(Bs_h, Bs_l, bb+2, bR.z);
            split_store(Bs_h, Bs_l, bb+3, bR.w);
        }
        __syncthreads();
        int k1 = k0 + 16;
        if (k1 < 4096) {
            aR[0] = (s0g >= 0) ? *(const float4*)&g_h[(long long)s0g*4096 + k1 + akq] : make_float4(0,0,0,0);
            aR[1] = (s1g >= 0) ? *(const float4*)&g_h[(long long)s1g*4096 + k1 + akq] : make_float4(0,0,0,0);
            bR = *(const float4*)&Be[(long long)(k1 + bkk) * 1024 + n0 + bnq];
        }
        #pragma unroll
        for (int kk = 0; kk < 16; kk += 8) {
            unsigned ah[2][4], al[2][4];
            #pragma unroll
            for (int mt = 0; mt < 2; mt++) {
                int rb = wm + mt*16 + g;
                int i0 = rb*20 + kk + tig, i1 = (rb+8)*20 + kk + tig;
                ah[mt][0] = As_h[i0];   al[mt][0] = As_l[i0];
                ah[mt][1] = As_h[i1];   al[mt][1] = As_l[i1];
                ah[mt][2] = As_h[i0+4]; al[mt][2] = As_l[i0+4];
                ah[mt][3] = As_h[i1+4]; al[mt][3] = As_l[i1+4];
            }
            unsigned bh[4][2], bl[4][2];
            #pragma unroll
            for (int nt = 0; nt < 4; nt++) {
                int nb = wn + nt*8 + g;
                int j0 = (kk+tig)*72 + nb, j1 = (kk+tig+4)*72 + nb;
                bh[nt][0] = Bs_h[j0]; bl[nt][0] = Bs_l[j0];
                bh[nt][1] = Bs_h[j1]; bl[nt][1] = Bs_l[j1];
            }
            #pragma unroll
            for (int mt = 0; mt < 2; mt++)
                #pragma unroll
                for (int nt = 0; nt < 4; nt++) {
                    mma8(c[mt][nt], ah[mt], bh[nt]);
                    mma8(c[mt][nt], ah[mt], bl[nt]);
                    mma8(c[mt][nt], al[mt], bh[nt]);
                }
        }
        __syncthreads();
    }

    #pragma unroll
    for (int mt = 0; mt < 2; mt++) {
        int lr0 = wm + mt*16 + g;
        int s0 = slots[lr0], s1 = slots[lr0 + 8];
        #pragma unroll
        for (int nt = 0; nt < 4; nt++) {
            int col = n0 + wn + nt*8 + tig*2;
            float bv0 = b2[e*1024 + col], bv1 = b2[e*1024 + col + 1];
            if (s0 >= 0) {
                g_eo[(long long)s0*1024 + col]     = c[mt][nt][0] + bv0;
                g_eo[(long long)s0*1024 + col + 1] = c[mt][nt][1] + bv1;
            }
            if (s1 >= 0) {
                g_eo[(long long)s1*1024 + col]     = c[mt][nt][2] + bv0;
                g_eo[(long long)s1*1024 + col + 1] = c[mt][nt][3] + bv1;
            }
        }
    }
}

__global__ void combine_k(const float* __restrict__ x, float* __restrict__ out) {
    int idx = blockIdx.x * 256 + threadIdx.x;
    int t = idx >> 10, d = idx & 1023;
    float v = x[idx];
    v += g_probs[2*t]     * g_eo[(long long)(2*t)     * 1024 + d];
    v += g_probs[2*t + 1] * g_eo[(long long)(2*t + 1) * 1024 + d];
    out[idx] = v;
}

// ---------------- launcher ----------------
extern "C" void kernel_launch(void* const* d_in, const int* in_sizes, int n_in,
                              void* d_out, int out_size) {
    const float* q        = (const float*)d_in[0];
    const float* kv       = (const float*)d_in[1];
    const float* ln_cq_g  = (const float*)d_in[2];
    const float* ln_cq_b  = (const float*)d_in[3];
    const float* ln_ckv_g = (const float*)d_in[4];
    const float* ln_ckv_b = (const float*)d_in[5];
    const float* ln_s_g   = (const float*)d_in[6];
    const float* ln_s_b   = (const float*)d_in[7];
    const float* ln_m_g   = (const float*)d_in[8];
    const float* ln_m_b   = (const float*)d_in[9];
    const float* ca_in_w  = (const float*)d_in[10];
    const float* ca_in_b  = (const float*)d_in[11];
    const float* ca_out_w = (const float*)d_in[12];
    const float* ca_out_b = (const float*)d_in[13];
    const float* sa_in_w  = (const float*)d_in[14];
    const float* sa_in_b  = (const float*)d_in[15];
    const float* sa_out_w = (const float*)d_in[16];
    const float* sa_out_b = (const float*)d_in[17];
    const float* moe_rw   = (const float*)d_in[18];
    const float* moe_rb   = (const float*)d_in[19];
    const float* moe_nw   = (const float*)d_in[20];
    const float* moe_nb   = (const float*)d_in[21];
    const float* moe_w1   = (const float*)d_in[22];
    const float* moe_b1   = (const float*)d_in[23];
    const float* moe_w2   = (const float*)d_in[24];
    const float* moe_b2   = (const float*)d_in[25];
    float* out = (float*)d_out;

    float *p_x, *p_ln1, *p_lnkv, *p_qp, *p_kvp, *p_scores, *p_ao;
    cudaGetSymbolAddress((void**)&p_x,      g_x);
    cudaGetSymbolAddress((void**)&p_ln1,    g_ln1);
    cudaGetSymbolAddress((void**)&p_lnkv,   g_lnkv);
    cudaGetSymbolAddress((void**)&p_qp,     g_qp);
    cudaGetSymbolAddress((void**)&p_kvp,    g_kvp);
    cudaGetSymbolAddress((void**)&p_scores, g_scores);
    cudaGetSymbolAddress((void**)&p_ao,     g_ao);

    const long long ZL = 0;

    // ===== Cross-attention =====
    ln_k<<<TQ, 256>>>(q,  p_ln1,  ln_cq_g,  ln_cq_b);
    ln_k<<<TKV, 256>>>(kv, p_lnkv, ln_ckv_g, ln_ckv_b);

    mma_gemm<true><<<dim3(16, 16, 1), 256>>>(p_ln1, 1024, ZL, ZL,
        ca_in_w, 1024, ZL, ZL, p_qp, 1024, ZL, ZL,
        TQ, 1024, 1024, 1, ca_in_b, 1.0f, nullptr);
    mma_gemm<true><<<dim3(32, 32, 1), 256>>>(p_lnkv, 1024, ZL, ZL,
        ca_in_w + 1024*1024, 1024, ZL, ZL, p_kvp, 2048, ZL, ZL,
        TKV, 2048, 1024, 1, ca_in_b + 1024, 1.0f, nullptr);
    mma_gemm<true><<<dim3(32, 8, 32), 256>>>(
        p_qp, 1024, (long long)NQv*1024, 64,
        p_kvp, 2048, (long long)NKVv*2048, 64,
        p_scores, 2048, (long long)Hv*NQv*NKVv, (long long)NQv*NKVv,
        1024, 2048, 64, 16, nullptr, 0.125f, nullptr);
    softmax_k<<<Bv*Hv*NQv, 256>>>(p_scores, 2048);
    mma_gemm<false><<<dim3(1, 8, 32), 256>>>(
        p_scores, 2048, (long long)Hv*NQv*NKVv, (long long)NQv*NKVv,
        p_kvp + 1024, 2048, (long long)NKVv*2048, 64,
        p_ao, 1024, (long long)NQv*1024, 64,
        1024, 64, 2048, 16, nullptr, 1.0f, nullptr);
    mma_gemm<true><<<dim3(16, 16, 1), 256>>>(p_ao, 1024, ZL, ZL,
        ca_out_w, 1024, ZL, ZL, p_x, 1024, ZL, ZL,
        TQ, 1024, 1024, 1, ca_out_b, 1.0f, q);

    // ===== Self-attention =====
    ln_k<<<TQ, 256>>>(p_x, p_ln1, ln_s_g, ln_s_b);
    mma_gemm<true><<<dim3(48, 16, 1), 256>>>(p_ln1, 1024, ZL, ZL,
        sa_in_w, 1024, ZL, ZL, p_kvp, 3072, ZL, ZL,
        TQ, 3072, 1024, 1, sa_in_b, 1.0f, nullptr);
    mma_gemm<true><<<dim3(16, 8, 32), 256>>>(
        p_kvp, 3072, (long long)NQv*3072, 64,
        p_kvp + 1024, 3072, (long long)NQv*3072, 64,
        p_scores, 1024, (long long)Hv*NQv*NQv, (long long)NQv*NQv,
        1024, 1024, 64, 16, nullptr, 0.125f, nullptr);
    softmax_k<<<Bv*Hv*NQv, 256>>>(p_scores, 1024);
    mma_gemm<false><<<dim3(1, 8, 32), 256>>>(
        p_scores, 1024, (long long)Hv*NQv*NQv, (long long)NQv*NQv,
        p_kvp + 2048, 3072, (long long)NQv*3072, 64,
        p_ao, 1024, (long long)NQv*1024, 64,
        1024, 64, 1024, 16, nullptr, 1.0f, nullptr);
    mma_gemm<true><<<dim3(16, 16, 1), 256>>>(p_ao, 1024, ZL, ZL,
        sa_out_w, 1024, ZL, ZL, p_x, 1024, ZL, ZL,
        TQ, 1024, 1024, 1, sa_out_b, 1.0f, p_x);

    // ===== MoE =====
    ln_k<<<TQ, 256>>>(p_x, p_ln1, ln_m_g, ln_m_b);
    zero_counts_k<<<1, 32>>>();
    router_k<<<TQ, 256>>>(p_ln1, moe_rw, moe_rb, moe_nw, moe_nb);
    moe_mma1<<<dim3(64, 16, 8), 256>>>(p_ln1, moe_w1, moe_b1);
    moe_mma2<<<dim3(16, 16, 8), 256>>>(moe_w2, moe_b2);
    combine_k<<<(TQ*Dv)/256, 256>>>(p_x, out);
}

// round 6
// speedup vs baseline: 1.0718x; 1.0718x over previous
#include <cuda_runtime.h>
#include <math.h>
#include <stdint.h>

// Problem dims
#define Bv    2
#define NQv   1024
#define NKVv  2048
#define Dv    1024
#define Hv    16
#define DHv   64
#define Ev    8
#define FFv   4096
#define TQ    (Bv*NQv)
#define TKV   (Bv*NKVv)
#define MAXTOK 2048

// ---------------- scratch ----------------
__device__ float g_x[TQ*Dv];
__device__ float g_ln1[TQ*Dv];
__device__ float g_lnkv[TKV*Dv];
__device__ float g_qp[TQ*Dv];
__device__ float g_kvp[TKV*2048];
__device__ float g_scores[(size_t)Bv*Hv*NQv*NKVv];
__device__ float g_ao[TQ*Dv];
__device__ float g_h[(size_t)TQ*2*FFv];
__device__ float g_eo[(size_t)TQ*2*Dv];
__device__ float g_probs[TQ*2];
__device__ int   g_counts[Ev];
__device__ int   g_elist[Ev*MAXTOK];

// ---------------- layernorm ----------------
__global__ void ln_k(const float* __restrict__ x, float* __restrict__ y,
                     const float* __restrict__ g, const float* __restrict__ b) {
    long row = blockIdx.x;
    const float* xr = x + row * 1024;
    float* yr = y + row * 1024;
    __shared__ float sm[1024];
    __shared__ float red[256];
    int tid = threadIdx.x;
    float s = 0.f;
    #pragma unroll
    for (int i = 0; i < 4; i++) { float v = xr[tid + (i<<8)]; sm[tid + (i<<8)] = v; s += v; }
    red[tid] = s; __syncthreads();
    for (int st = 128; st > 0; st >>= 1) { if (tid < st) red[tid] += red[tid + st]; __syncthreads(); }
    float mean = red[0] * (1.0f/1024.0f); __syncthreads();
    float s2 = 0.f;
    #pragma unroll
    for (int i = 0; i < 4; i++) { float d = sm[tid + (i<<8)] - mean; s2 += d*d; }
    red[tid] = s2; __syncthreads();
    for (int st = 128; st > 0; st >>= 1) { if (tid < st) red[tid] += red[tid + st]; __syncthreads(); }
    float var = red[0] * (1.0f/1024.0f);
    float rstd = rsqrtf(var + 1e-5f);
    #pragma unroll
    for (int i = 0; i < 4; i++) { int c = tid + (i<<8); yr[c] = (sm[c]-mean)*rstd*g[c] + b[c]; }
}

// ---------------- softmax ----------------
__global__ void softmax_k(float* __restrict__ S, int L) {
    float* r = S + (size_t)blockIdx.x * L;
    int tid = threadIdx.x;
    __shared__ float red[256];
    int cnt = L >> 8;
    float v[8];
    float mx = -3.4e38f;
    for (int i = 0; i < cnt; i++) { v[i] = r[tid + (i<<8)]; mx = fmaxf(mx, v[i]); }
    red[tid] = mx; __syncthreads();
    for (int st = 128; st > 0; st >>= 1) { if (tid < st) red[tid] = fmaxf(red[tid], red[tid+st]); __syncthreads(); }
    mx = red[0]; __syncthreads();
    float sum = 0.f;
    for (int i = 0; i < cnt; i++) { v[i] = expf(v[i]-mx); sum += v[i]; }
    red[tid] = sum; __syncthreads();
    for (int st = 128; st > 0; st >>= 1) { if (tid < st) red[tid] += red[tid+st]; __syncthreads(); }
    float inv = 1.0f / red[0];
    for (int i = 0; i < cnt; i++) r[tid + (i<<8)] = v[i]*inv;
}

// ---------------- tf32 mma helpers ----------------
__device__ __forceinline__ unsigned f2tf(float x) {
    unsigned r; asm("cvt.rna.tf32.f32 %0, %1;" : "=r"(r) : "f"(x)); return r;
}
__device__ __forceinline__ uint2 split2(float x) {
    unsigned hh = f2tf(x);
    return make_uint2(hh, f2tf(x - __uint_as_float(hh)));
}
__device__ __forceinline__ void mma8(float* c, const unsigned* a, const unsigned* b) {
    asm volatile("mma.sync.aligned.m16n8k8.row.col.f32.tf32.tf32.f32 "
        "{%0,%1,%2,%3},{%4,%5,%6,%7},{%8,%9},{%0,%1,%2,%3};"
        : "+f"(c[0]), "+f"(c[1]), "+f"(c[2]), "+f"(c[3])
        : "r"(a[0]), "r"(a[1]), "r"(a[2]), "r"(a[3]), "r"(b[0]), "r"(b[1]));
}
// pack 2 split values into a uint4 {h0,l0,h1,l1}
__device__ __forceinline__ uint4 splitpack(float x0, float x1) {
    uint2 a = split2(x0), b = split2(x1);
    return make_uint4(a.x, a.y, b.x, b.y);
}

// B stride (uint2 units)
#define BS_BT  20
#define BS_NT  76

// ---------------- 3xTF32 GEMM: interleaved hi/lo smem (uint2) ----------------
// C[M,N] = alpha * A[M,K] * op(B) + bias + res
// BT=true : B is [N,K] row-major;  BT=false: B is [K,N] row-major
template<bool BT>
__global__ __launch_bounds__(256, 2) void mma_gemm(
    const float* __restrict__ A, int lda, long long sAo, long long sAi,
    const float* __restrict__ B, int ldb, long long sBo, long long sBi,
    float* __restrict__ C, int ldc, long long sCo, long long sCi,
    int M, int N, int K, int inner,
    const float* __restrict__ bias, float alpha, const float* __restrict__ res)
{
    int z = blockIdx.z;
    int zo = z / inner, zi = z - zo * inner;
    A += zo * sAo + zi * sAi;
    B += zo * sBo + zi * sBi;
    C += zo * sCo + zi * sCi;
    if (res) res += zo * sCo + zi * sCi;

    __shared__ uint2 As2[2560];                       // [m][k] stride 20
    __shared__ uint2 Bs2[BT ? 1280 : (16*BS_NT)];     // BT: [n][k] s20 ; !BT: [k][n] s76

    int tid = threadIdx.x, lane = tid & 31, warp = tid >> 5;
    int g = lane >> 2, tig = lane & 3;
    int wm = (warp & 3) * 32, wn = (warp >> 2) * 32;
    int m0 = blockIdx.y * 128, n0 = blockIdx.x * 64;

    float c[2][4][4] = {};
    float4 aR[2], bR;

    int ar0 = tid >> 2, akq = (tid & 3) << 2;
    int bn, bkq, bkk, bnq;
    if (BT) { bn = tid >> 2; bkq = (tid & 3) << 2; bkk = 0; bnq = 0; }
    else    { bkk = tid >> 4; bnq = (tid & 15) << 2; bn = 0; bkq = 0; }

    // prologue: load tile 0
    {
        int gm0 = m0 + ar0, gm1 = m0 + ar0 + 64;
        aR[0] = (gm0 < M) ? *(const float4*)&A[(long long)gm0 * lda + akq] : make_float4(0,0,0,0);
        aR[1] = (gm1 < M) ? *(const float4*)&A[(long long)gm1 * lda + akq] : make_float4(0,0,0,0);
        if (BT) bR = *(const float4*)&B[(long long)(n0 + bn) * ldb + bkq];
        else    bR = *(const float4*)&B[(long long)bkk * ldb + n0 + bnq];
    }

    for (int k0 = 0; k0 < K; k0 += 16) {
        // stage regs -> smem (split, interleaved): 6x STS.128 per thread
        {
            int base0 = ar0*20 + akq, base1 = (ar0+64)*20 + akq;
            *(uint4*)&As2[base0]   = splitpack(aR[0].x, aR[0].y);
            *(uint4*)&As2[base0+2] = splitpack(aR[0].z, aR[0].w);
            *(uint4*)&As2[base1]   = splitpack(aR[1].x, aR[1].y);
            *(uint4*)&As2[base1+2] = splitpack(aR[1].z, aR[1].w);
            int bb = BT ? (bn*BS_BT + bkq) : (bkk*BS_NT + bnq);
            *(uint4*)&Bs2[bb]   = splitpack(bR.x, bR.y);
            *(uint4*)&Bs2[bb+2] = splitpack(bR.z, bR.w);
        }
        __syncthreads();

        // prefetch next tile (overlaps with MMA below)
        int k1 = k0 + 16;
        if (k1 < K) {
            int gm0 = m0 + ar0, gm1 = m0 + ar0 + 64;
            aR[0] = (gm0 < M) ? *(const float4*)&A[(long long)gm0 * lda + k1 + akq] : make_float4(0,0,0,0);
            aR[1] = (gm1 < M) ? *(const float4*)&A[(long long)gm1 * lda + k1 + akq] : make_float4(0,0,0,0);
            if (BT) bR = *(const float4*)&B[(long long)(n0 + bn) * ldb + k1 + bkq];
            else    bR = *(const float4*)&B[(long long)(k1 + bkk) * ldb + n0 + bnq];
        }

        #pragma unroll
        for (int kk = 0; kk < 16; kk += 8) {
            unsigned ah[2][4], al[2][4];
            #pragma unroll
            for (int mt = 0; mt < 2; mt++) {
                int rb = wm + mt*16 + g;
                int i0 = rb*20 + kk + tig, i1 = (rb+8)*20 + kk + tig;
                uint2 a0 = As2[i0], a1 = As2[i1], a2 = As2[i0+4], a3 = As2[i1+4];
                ah[mt][0] = a0.x; al[mt][0] = a0.y;
                ah[mt][1] = a1.x; al[mt][1] = a1.y;
                ah[mt][2] = a2.x; al[mt][2] = a2.y;
                ah[mt][3] = a3.x; al[mt][3] = a3.y;
            }
            unsigned bh[4][2], bl[4][2];
            #pragma unroll
            for (int nt = 0; nt < 4; nt++) {
                int nb = wn + nt*8 + g;
                int j0, j1;
                if (BT) { j0 = nb*BS_BT + kk + tig;  j1 = j0 + 4; }
                else    { j0 = (kk+tig)*BS_NT + nb;  j1 = (kk+tig+4)*BS_NT + nb; }
                uint2 b0 = Bs2[j0], b1 = Bs2[j1];
                bh[nt][0] = b0.x; bl[nt][0] = b0.y;
                bh[nt][1] = b1.x; bl[nt][1] = b1.y;
            }
            #pragma unroll
            for (int mt = 0; mt < 2; mt++)
                #pragma unroll
                for (int nt = 0; nt < 4; nt++) {
                    mma8(c[mt][nt], ah[mt], bh[nt]);
                    mma8(c[mt][nt], ah[mt], bl[nt]);
                    mma8(c[mt][nt], al[mt], bh[nt]);
                }
        }
        __syncthreads();
    }

    // ---- epilogue ----
    #pragma unroll
    for (int mt = 0; mt < 2; mt++) {
        int r0 = m0 + wm + mt*16 + g;
        #pragma unroll
        for (int nt = 0; nt < 4; nt++) {
            int col = n0 + wn + nt*8 + tig*2;
            float bv0 = bias ? bias[col]   : 0.f;
            float bv1 = bias ? bias[col+1] : 0.f;
            if (r0 < M) {
                float v0 = alpha*c[mt][nt][0] + bv0;
                float v1 = alpha*c[mt][nt][1] + bv1;
                if (res) { v0 += res[(long long)r0*ldc + col]; v1 += res[(long long)r0*ldc + col + 1]; }
                C[(long long)r0*ldc + col]     = v0;
                C[(long long)r0*ldc + col + 1] = v1;
            }
            int r1 = r0 + 8;
            if (r1 < M) {
                float v2 = alpha*c[mt][nt][2] + bv0;
                float v3 = alpha*c[mt][nt][3] + bv1;
                if (res) { v2 += res[(long long)r1*ldc + col]; v3 += res[(long long)r1*ldc + col + 1]; }
                C[(long long)r1*ldc + col]     = v2;
                C[(long long)r1*ldc + col + 1] = v3;
            }
        }
    }
}

// ---------------- JAX threefry2x32 / normal ----------------
__device__ __forceinline__ void threefry42(unsigned c0, unsigned c1, unsigned& o0, unsigned& o1) {
    const unsigned k0 = 0u, k1 = 42u;
    const unsigned k2 = 0x1BD11BDAu ^ k0 ^ k1;
    unsigned x0 = c0 + k0, x1 = c1 + k1;
#define TF_R(r) { x0 += x1; x1 = (x1 << r) | (x1 >> (32 - r)); x1 ^= x0; }
    TF_R(13) TF_R(15) TF_R(26) TF_R(6)   x0 += k1; x1 += k2 + 1u;
    TF_R(17) TF_R(29) TF_R(16) TF_R(24)  x0 += k2; x1 += k0 + 2u;
    TF_R(13) TF_R(15) TF_R(26) TF_R(6)   x0 += k0; x1 += k1 + 3u;
    TF_R(17) TF_R(29) TF_R(16) TF_R(24)  x0 += k1; x1 += k2 + 4u;
    TF_R(13) TF_R(15) TF_R(26) TF_R(6)   x0 += k2; x1 += k0 + 5u;
#undef TF_R
    o0 = x0; o1 = x1;
}

__device__ __forceinline__ float erfinv_f(float x) {
    float w = -log1pf(__fmul_rn(-x, x));
    float p;
    if (w < 5.0f) {
        w = __fadd_rn(w, -2.5f);
        p = 2.81022636e-08f;
        p = __fadd_rn(__fmul_rn(p, w),  3.43273939e-07f);
        p = __fadd_rn(__fmul_rn(p, w), -3.5233877e-06f);
        p = __fadd_rn(__fmul_rn(p, w), -4.39150654e-06f);
        p = __fadd_rn(__fmul_rn(p, w),  0.00021858087f);
        p = __fadd_rn(__fmul_rn(p, w), -0.00125372503f);
        p = __fadd_rn(__fmul_rn(p, w), -0.00417768164f);
        p = __fadd_rn(__fmul_rn(p, w),  0.246640727f);
        p = __fadd_rn(__fmul_rn(p, w),  1.50140941f);
    } else {
        w = __fadd_rn(sqrtf(w), -3.0f);
        p = -0.000200214257f;
        p = __fadd_rn(__fmul_rn(p, w),  0.000100950558f);
        p = __fadd_rn(__fmul_rn(p, w),  0.00134934322f);
        p = __fadd_rn(__fmul_rn(p, w), -0.00367342844f);
        p = __fadd_rn(__fmul_rn(p, w),  0.00573950773f);
        p = __fadd_rn(__fmul_rn(p, w), -0.0076224613f);
        p = __fadd_rn(__fmul_rn(p, w),  0.00943887047f);
        p = __fadd_rn(__fmul_rn(p, w),  1.00167406f);
        p = __fadd_rn(__fmul_rn(p, w),  2.83297682f);
    }
    return __fmul_rn(p, x);
}

// partitionable threefry: counter (0, i), bits = out0 ^ out1
__device__ __forceinline__ float jax_normal(int i) {
    unsigned o0, o1;
    threefry42(0u, (unsigned)i, o0, o1);
    unsigned bits = o0 ^ o1;
    unsigned fb = (bits >> 9) | 0x3f800000u;
    float u01 = __fadd_rn(__uint_as_float(fb), -1.0f);
    const float lo = -0.99999994f;
    float u = __fadd_rn(__fmul_rn(u01, 2.0f), lo);
    u = fmaxf(lo, u);
    return __fmul_rn(1.41421354f, erfinv_f(u));
}

// ---------------- MoE router ----------------
__global__ void zero_counts_k() { if (threadIdx.x < Ev) g_counts[threadIdx.x] = 0; }

__global__ void router_k(const float* __restrict__ xm,
                         const float* __restrict__ rw, const float* __restrict__ rb,
                         const float* __restrict__ nw, const float* __restrict__ nb) {
    int t = blockIdx.x;
    int tid = threadIdx.x;
    int w = tid >> 5, lane = tid & 31;
    __shared__ float sl[8], sn[8];
    const float* xr = xm + (long long)t * 1024;
    const float* rwe = rw + w * 1024;
    const float* nwe = nw + w * 1024;
    float sr = 0.f, s_n = 0.f;
    for (int d = lane; d < 1024; d += 32) {
        float xv = xr[d];
        sr  += xv * rwe[d];
        s_n += xv * nwe[d];
    }
    #pragma unroll
    for (int o = 16; o; o >>= 1) {
        sr  += __shfl_down_sync(0xffffffffu, sr, o);
        s_n += __shfl_down_sync(0xffffffffu, s_n, o);
    }
    if (lane == 0) { sl[w] = sr + rb[w]; sn[w] = s_n + nb[w]; }
    __syncthreads();
    if (tid == 0) {
        float noisy[8];
        #pragma unroll
        for (int e = 0; e < 8; e++) {
            float nrm = jax_normal(t * 8 + e);
            float zz = sn[e];
            float sp = fmaxf(zz, 0.f) + log1pf(expf(-fabsf(zz)));
            noisy[e] = sl[e] + nrm * sp;
        }
        int i1 = 0;
        #pragma unroll
        for (int e = 1; e < 8; e++) if (noisy[e] > noisy[i1]) i1 = e;
        int i2 = (i1 == 0) ? 1 : 0;
        #pragma unroll
        for (int e = 0; e < 8; e++) if (e != i1 && noisy[e] > noisy[i2]) i2 = e;
        float mx = noisy[i1];
        float e1 = expf(noisy[i1] - mx);
        float e2 = expf(noisy[i2] - mx);
        float Z  = e1 + e2;
        g_probs[2*t]   = e1 / Z;
        g_probs[2*t+1] = e2 / Z;
        int p1 = atomicAdd(&g_counts[i1], 1); g_elist[i1 * MAXTOK + p1] = 2*t;
        int p2 = atomicAdd(&g_counts[i2], 1); g_elist[i2 * MAXTOK + p2] = 2*t + 1;
    }
}

// ---------------- MoE tensor-core GEMMs (uint2 interleaved) ----------------
__global__ __launch_bounds__(256, 2) void moe_mma1(const float* __restrict__ xm,
                                                   const float* __restrict__ w1,
                                                   const float* __restrict__ b1) {
    int e = blockIdx.z;
    int cnt = g_counts[e];
    int m0 = blockIdx.y * 128;
    if (m0 >= cnt) return;
    int n0 = blockIdx.x * 64;

    __shared__ int slots[128];
    __shared__ uint2 As2[2560];
    __shared__ uint2 Bs2[16*BS_NT];

    int tid = threadIdx.x, lane = tid & 31, warp = tid >> 5;
    int g = lane >> 2, tig = lane & 3;
    int wm = (warp & 3) * 32, wn = (warp >> 2) * 32;
    if (tid < 128) slots[tid] = (m0 + tid < cnt) ? g_elist[e * MAXTOK + m0 + tid] : -1;
    __syncthreads();

    const float* Be = w1 + (long long)e * 1024 * 4096;
    float c[2][4][4] = {};
    float4 aR[2], bR;

    int ar0 = tid >> 2, akq = (tid & 3) << 2;
    int bkk = tid >> 4, bnq = (tid & 15) << 2;
    int s0g = slots[ar0], s1g = slots[ar0 + 64];

    aR[0] = (s0g >= 0) ? *(const float4*)&xm[(long long)(s0g >> 1)*1024 + akq] : make_float4(0,0,0,0);
    aR[1] = (s1g >= 0) ? *(const float4*)&xm[(long long)(s1g >> 1)*1024 + akq] : make_float4(0,0,0,0);
    bR = *(const float4*)&Be[(long long)bkk * 4096 + n0 + bnq];

    for (int k0 = 0; k0 < 1024; k0 += 16) {
        {
            int base0 = ar0*20 + akq, base1 = (ar0+64)*20 + akq;
            *(uint4*)&As2[base0]   = splitpack(aR[0].x, aR[0].y);
            *(uint4*)&As2[base0+2] = splitpack(aR[0].z, aR[0].w);
            *(uint4*)&As2[base1]   = splitpack(aR[1].x, aR[1].y);
            *(uint4*)&As2[base1+2] = splitpack(aR[1].z, aR[1].w);
            int bb = bkk*BS_NT + bnq;
            *(uint4*)&Bs2[bb]   = splitpack(bR.x, bR.y);
            *(uint4*)&Bs2[bb+2] = splitpack(bR.z, bR.w);
        }
        __syncthreads();
        int k1 = k0 + 16;
        if (k1 < 1024) {
            aR[0] = (s0g >= 0) ? *(const float4*)&xm[(long long)(s0g >> 1)*1024 + k1 + akq] : make_float4(0,0,0,0);
            aR[1] = (s1g >= 0) ? *(const float4*)&xm[(long long)(s1g >> 1)*1024 + k1 + akq] : make_float4(0,0,0,0);
            bR = *(const float4*)&Be[(long long)(k1 + bkk) * 4096 + n0 + bnq];
        }
        #pragma unroll
        for (int kk = 0; kk < 16; kk += 8) {
            unsigned ah[2][4], al[2][4];
            #pragma unroll
            for (int mt = 0; mt < 2; mt++) {
                int rb = wm + mt*16 + g;
                int i0 = rb*20 + kk + tig, i1 = (rb+8)*20 + kk + tig;
                uint2 a0 = As2[i0], a1 = As2[i1], a2 = As2[i0+4], a3 = As2[i1+4];
                ah[mt][0] = a0.x; al[mt][0] = a0.y;
                ah[mt][1] = a1.x; al[mt][1] = a1.y;
                ah[mt][2] = a2.x; al[mt][2] = a2.y;
                ah[mt][3] = a3.x; al[mt][3] = a3.y;
            }
            unsigned bh[4][2], bl[4][2];
            #pragma unroll
            for (int nt = 0; nt < 4; nt++) {
                int nb = wn + nt*8 + g;
                int j0 = (kk+tig)*BS_NT + nb, j1 = (kk+tig+4)*BS_NT + nb;
                uint2 b0 = Bs2[j0], b1 = Bs2[j1];
                bh[nt][0] = b0.x; bl[nt][0] = b0.y;
                bh[nt][1] = b1.x; bl[nt][1] = b1.y;
            }
            #pragma unroll
            for (int mt = 0; mt < 2; mt++)
                #pragma unroll
                for (int nt = 0; nt < 4; nt++) {
                    mma8(c[mt][nt], ah[mt], bh[nt]);
                    mma8(c[mt][nt], ah[mt], bl[nt]);
                    mma8(c[mt][nt], al[mt], bh[nt]);
                }
        }
        __syncthreads();
    }

    #pragma unroll
    for (int mt = 0; mt < 2; mt++) {
        int lr0 = wm + mt*16 + g;
        int s0 = slots[lr0], s1 = slots[lr0 + 8];
        #pragma unroll
        for (int nt = 0; nt < 4; nt++) {
            int col = n0 + wn + nt*8 + tig*2;
            float bv0 = b1[e*4096 + col], bv1 = b1[e*4096 + col + 1];
            if (s0 >= 0) {
                float v0 = c[mt][nt][0] + bv0;
                float v1 = c[mt][nt][1] + bv1;
                v0 = 0.5f * v0 * (1.0f + erff(v0 * 0.70710677f));
                v1 = 0.5f * v1 * (1.0f + erff(v1 * 0.70710677f));
                g_h[(long long)s0*4096 + col]     = v0;
                g_h[(long long)s0*4096 + col + 1] = v1;
            }
            if (s1 >= 0) {
                float v2 = c[mt][nt][2] + bv0;
                float v3 = c[mt][nt][3] + bv1;
                v2 = 0.5f * v2 * (1.0f + erff(v2 * 0.70710677f));
                v3 = 0.5f * v3 * (1.0f + erff(v3 * 0.70710677f));
                g_h[(long long)s1*4096 + col]     = v2;
                g_h[(long long)s1*4096 + col + 1] = v3;
            }
        }
    }
}

__global__ __launch_bounds__(256, 2) void moe_mma2(const float* __restrict__ w2,
                                                   const float* __restrict__ b2) {
    int e = blockIdx.z;
    int cnt = g_counts[e];
    int m0 = blockIdx.y * 128;
    if (m0 >= cnt) return;
    int n0 = blockIdx.x * 64;

    __shared__ int slots[128];
    __shared__ uint2 As2[2560];
    __shared__ uint2 Bs2[16*BS_NT];

    int tid = threadIdx.x, lane = tid & 31, warp = tid >> 5;
    int g = lane >> 2, tig = lane & 3;
    int wm = (warp & 3) * 32, wn = (warp >> 2) * 32;
    if (tid < 128) slots[tid] = (m0 + tid < cnt) ? g_elist[e * MAXTOK + m0 + tid] : -1;
    __syncthreads();

    const float* Be = w2 + (long long)e * 4096 * 1024;
    float c[2][4][4] = {};
    float4 aR[2], bR;

    int ar0 = tid >> 2, akq = (tid & 3) << 2;
    int bkk = tid >> 4, bnq = (tid & 15) << 2;
    int s0g = slots[ar0], s1g = slots[ar0 + 64];

    aR[0] = (s0g >= 0) ? *(const float4*)&g_h[(long long)s0g*4096 + akq] : make_float4(0,0,0,0);
    aR[1] = (s1g >= 0) ? *(const float4*)&g_h[(long long)s1g*4096 + akq] : make_float4(0,0,0,0);
    bR = *(const float4*)&Be[(long long)bkk * 1024 + n0 + bnq];

    for (int k0 = 0; k0 < 4096; k0 += 16) {
        {
            int base0 = ar0*20 + akq, base1 = (ar0+64)*20 + akq;
            *(uint4*)&As2[base0]   = splitpack(aR[0].x, aR[0].y);
            *(uint4*)&As2[base0+2] = splitpack(aR[0].z, aR[0].w);
            *(uint4*)&As2[base1]   = splitpack(aR[1].x, aR[1].y);
            *(uint4*)&As2[base1+2] = splitpack(aR[1].z, aR[1].w);
            int bb = bkk*BS_NT + bnq;
            *(uint4*)&Bs2[bb]   = splitpack(bR.x, bR.y);
            *(uint4*)&Bs2[bb+2] = splitpack(bR.z, bR.w);
        }
        __syncthreads();
        int k1 = k0 + 16;
        if (k1 < 4096) {
            aR[0] = (s0g >= 0) ? *(const float4*)&g_h[(long long)s0g*4096 + k1 + akq] : make_float4(0,0,0,0);
            aR[1] = (s1g >= 0) ? *(const float4*)&g_h[(long long)s1g*4096 + k1 + akq] : make_float4(0,0,0,0);
            bR = *(const float4*)&Be[(long long)(k1 + bkk) * 1024 + n0 + bnq];
        }
        #pragma unroll
        for (int kk = 0; kk < 16; kk += 8) {
            unsigned ah[2][4], al[2][4];
            #pragma unroll
            for (int mt = 0; mt < 2; mt++) {
                int rb = wm + mt*16 + g;
                int i0 = rb*20 + kk + tig, i1 = (rb+8)*20 + kk + tig;
                uint2 a0 = As2[i0], a1 = As2[i1], a2 = As2[i0+4], a3 = As2[i1+4];
                ah[mt][0] = a0.x; al[mt][0] = a0.y;
                ah[mt][1] = a1.x; al[mt][1] = a1.y;
                ah[mt][2] = a2.x; al[mt][2] = a2.y;
                ah[mt][3] = a3.x; al[mt][3] = a3.y;
            }
            unsigned bh[4][2], bl[4][2];
            #pragma unroll
            for (int nt = 0; nt < 4; nt++) {
                int nb = wn + nt*8 + g;
                int j0 = (kk+tig)*BS_NT + nb, j1 = (kk+tig+4)*BS_NT + nb;
                uint2 b0 = Bs2[j0], b1 = Bs2[j1];
                bh[nt][0] = b0.x; bl[nt][0] = b0.y;
                bh[nt][1] = b1.x; bl[nt][1] = b1.y;
            }
            #pragma unroll
            for (int mt = 0; mt < 2; mt++)
                #pragma unroll
                for (int nt = 0; nt < 4; nt++) {
                    mma8(c[mt][nt], ah[mt], bh[nt]);
                    mma8(c[mt][nt], ah[mt], bl[nt]);
                    mma8(c[mt][nt], al[mt], bh[nt]);
                }
        }
        __syncthreads();
    }

    #pragma unroll
    for (int mt = 0; mt < 2; mt++) {
        int lr0 = wm + mt*16 + g;
        int s0 = slots[lr0], s1 = slots[lr0 + 8];
        #pragma unroll
        for (int nt = 0; nt < 4; nt++) {
            int col = n0 + wn + nt*8 + tig*2;
            float bv0 = b2[e*1024 + col], bv1 = b2[e*1024 + col + 1];
            if (s0 >= 0) {
                g_eo[(long long)s0*1024 + col]     = c[mt][nt][0] + bv0;
                g_eo[(long long)s0*1024 + col + 1] = c[mt][nt][1] + bv1;
            }
            if (s1 >= 0) {
                g_eo[(long long)s1*1024 + col]     = c[mt][nt][2] + bv0;
                g_eo[(long long)s1*1024 + col + 1] = c[mt][nt][3] + bv1;
            }
        }
    }
}

__global__ void combine_k(const float* __restrict__ x, float* __restrict__ out) {
    int idx = blockIdx.x * 256 + threadIdx.x;
    int t = idx >> 10, d = idx & 1023;
    float v = x[idx];
    v += g_probs[2*t]     * g_eo[(long long)(2*t)     * 1024 + d];
    v += g_probs[2*t + 1] * g_eo[(long long)(2*t + 1) * 1024 + d];
    out[idx] = v;
}

// ---------------- launcher ----------------
extern "C" void kernel_launch(void* const* d_in, const int* in_sizes, int n_in,
                              void* d_out, int out_size) {
    const float* q        = (const float*)d_in[0];
    const float* kv       = (const float*)d_in[1];
    const float* ln_cq_g  = (const float*)d_in[2];
    const float* ln_cq_b  = (const float*)d_in[3];
    const float* ln_ckv_g = (const float*)d_in[4];
    const float* ln_ckv_b = (const float*)d_in[5];
    const float* ln_s_g   = (const float*)d_in[6];
    const float* ln_s_b   = (const float*)d_in[7];
    const float* ln_m_g   = (const float*)d_in[8];
    const float* ln_m_b   = (const float*)d_in[9];
    const float* ca_in_w  = (const float*)d_in[10];
    const float* ca_in_b  = (const float*)d_in[11];
    const float* ca_out_w = (const float*)d_in[12];
    const float* ca_out_b = (const float*)d_in[13];
    const float* sa_in_w  = (const float*)d_in[14];
    const float* sa_in_b  = (const float*)d_in[15];
    const float* sa_out_w = (const float*)d_in[16];
    const float* sa_out_b = (const float*)d_in[17];
    const float* moe_rw   = (const float*)d_in[18];
    const float* moe_rb   = (const float*)d_in[19];
    const float* moe_nw   = (const float*)d_in[20];
    const float* moe_nb   = (const float*)d_in[21];
    const float* moe_w1   = (const float*)d_in[22];
    const float* moe_b1   = (const float*)d_in[23];
    const float* moe_w2   = (const float*)d_in[24];
    const float* moe_b2   = (const float*)d_in[25];
    float* out = (float*)d_out;

    float *p_x, *p_ln1, *p_lnkv, *p_qp, *p_kvp, *p_scores, *p_ao;
    cudaGetSymbolAddress((void**)&p_x,      g_x);
    cudaGetSymbolAddress((void**)&p_ln1,    g_ln1);
    cudaGetSymbolAddress((void**)&p_lnkv,   g_lnkv);
    cudaGetSymbolAddress((void**)&p_qp,     g_qp);
    cudaGetSymbolAddress((void**)&p_kvp,    g_kvp);
    cudaGetSymbolAddress((void**)&p_scores, g_scores);
    cudaGetSymbolAddress((void**)&p_ao,     g_ao);

    const long long ZL = 0;

    // ===== Cross-attention =====
    ln_k<<<TQ, 256>>>(q,  p_ln1,  ln_cq_g,  ln_cq_b);
    ln_k<<<TKV, 256>>>(kv, p_lnkv, ln_ckv_g, ln_ckv_b);

    mma_gemm<true><<<dim3(16, 16, 1), 256>>>(p_ln1, 1024, ZL, ZL,
        ca_in_w, 1024, ZL, ZL, p_qp, 1024, ZL, ZL,
        TQ, 1024, 1024, 1, ca_in_b, 1.0f, nullptr);
    mma_gemm<true><<<dim3(32, 32, 1), 256>>>(p_lnkv, 1024, ZL, ZL,
        ca_in_w + 1024*1024, 1024, ZL, ZL, p_kvp, 2048, ZL, ZL,
        TKV, 2048, 1024, 1, ca_in_b + 1024, 1.0f, nullptr);
    mma_gemm<true><<<dim3(32, 8, 32), 256>>>(
        p_qp, 1024, (long long)NQv*1024, 64,
        p_kvp, 2048, (long long)NKVv*2048, 64,
        p_scores, 2048, (long long)Hv*NQv*NKVv, (long long)NQv*NKVv,
        1024, 2048, 64, 16, nullptr, 0.125f, nullptr);
    softmax_k<<<Bv*Hv*NQv, 256>>>(p_scores, 2048);
    mma_gemm<false><<<dim3(1, 8, 32), 256>>>(
        p_scores, 2048, (long long)Hv*NQv*NKVv, (long long)NQv*NKVv,
        p_kvp + 1024, 2048, (long long)NKVv*2048, 64,
        p_ao, 1024, (long long)NQv*1024, 64,
        1024, 64, 2048, 16, nullptr, 1.0f, nullptr);
    mma_gemm<true><<<dim3(16, 16, 1), 256>>>(p_ao, 1024, ZL, ZL,
        ca_out_w, 1024, ZL, ZL, p_x, 1024, ZL, ZL,
        TQ, 1024, 1024, 1, ca_out_b, 1.0f, q);

    // ===== Self-attention =====
    ln_k<<<TQ, 256>>>(p_x, p_ln1, ln_s_g, ln_s_b);
    mma_gemm<true><<<dim3(48, 16, 1), 256>>>(p_ln1, 1024, ZL, ZL,
        sa_in_w, 1024, ZL, ZL, p_kvp, 3072, ZL, ZL,
        TQ, 3072, 1024, 1, sa_in_b, 1.0f, nullptr);
    mma_gemm<true><<<dim3(16, 8, 32), 256>>>(
        p_kvp, 3072, (long long)NQv*3072, 64,
        p_kvp + 1024, 3072, (long long)NQv*3072, 64,
        p_scores, 1024, (long long)Hv*NQv*NQv, (long long)NQv*NQv,
        1024, 1024, 64, 16, nullptr, 0.125f, nullptr);
    softmax_k<<<Bv*Hv*NQv, 256>>>(p_scores, 1024);
    mma_gemm<false><<<dim3(1, 8, 32), 256>>>(
        p_scores, 1024, (long long)Hv*NQv*NQv, (long long)NQv*NQv,
        p_kvp + 2048, 3072, (long long)NQv*3072, 64,
        p_ao, 1024, (long long)NQv*1024, 64,
        1024, 64, 1024, 16, nullptr, 1.0f, nullptr);
    mma_gemm<true><<<dim3(16, 16, 1), 256>>>(p_ao, 1024, ZL, ZL,
        sa_out_w, 1024, ZL, ZL, p_x, 1024, ZL, ZL,
        TQ, 1024, 1024, 1, sa_out_b, 1.0f, p_x);

    // ===== MoE =====
    ln_k<<<TQ, 256>>>(p_x, p_ln1, ln_m_g, ln_m_b);
    zero_counts_k<<<1, 32>>>();
    router_k<<<TQ, 256>>>(p_ln1, moe_rw, moe_rb, moe_nw, moe_nb);
    moe_mma1<<<dim3(64, 16, 8), 256>>>(p_ln1, moe_w1, moe_b1);
    moe_mma2<<<dim3(16, 16, 8), 256>>>(moe_w2, moe_b2);
    combine_k<<<(TQ*Dv)/256, 256>>>(p_x, out);
}

// round 7
// speedup vs baseline: 2.1535x; 2.0092x over previous
#include <cuda_runtime.h>
#include <cuda_bf16.h>
#include <math.h>
#include <stdint.h>

// Problem dims
#define Bv    2
#define NQv   1024
#define NKVv  2048
#define Dv    1024
#define Hv    16
#define DHv   64
#define Ev    8
#define FFv   4096
#define TQ    (Bv*NQv)
#define TKV   (Bv*NKVv)
#define MAXTOK 2048

// ---------------- scratch ----------------
__device__ float g_x[TQ*Dv];
__device__ float g_ln1[TQ*Dv];
__device__ float g_lnkv[TKV*Dv];
__device__ float g_qp[TQ*Dv];
__device__ float g_kvp[TKV*2048];
__device__ float g_scores[(size_t)Bv*Hv*NQv*NKVv];
__device__ float g_ao[TQ*Dv];
__device__ float g_h[(size_t)TQ*2*FFv];
__device__ float g_eo[(size_t)TQ*2*Dv];
__device__ float g_probs[TQ*2];
__device__ int   g_counts[Ev];
__device__ int   g_elist[Ev*MAXTOK];

// ---------------- layernorm ----------------
__global__ void ln_k(const float* __restrict__ x, float* __restrict__ y,
                     const float* __restrict__ g, const float* __restrict__ b) {
    long row = blockIdx.x;
    const float* xr = x + row * 1024;
    float* yr = y + row * 1024;
    __shared__ float sm[1024];
    __shared__ float red[256];
    int tid = threadIdx.x;
    float s = 0.f;
    #pragma unroll
    for (int i = 0; i < 4; i++) { float v = xr[tid + (i<<8)]; sm[tid + (i<<8)] = v; s += v; }
    red[tid] = s; __syncthreads();
    for (int st = 128; st > 0; st >>= 1) { if (tid < st) red[tid] += red[tid + st]; __syncthreads(); }
    float mean = red[0] * (1.0f/1024.0f); __syncthreads();
    float s2 = 0.f;
    #pragma unroll
    for (int i = 0; i < 4; i++) { float d = sm[tid + (i<<8)] - mean; s2 += d*d; }
    red[tid] = s2; __syncthreads();
    for (int st = 128; st > 0; st >>= 1) { if (tid < st) red[tid] += red[tid + st]; __syncthreads(); }
    float var = red[0] * (1.0f/1024.0f);
    float rstd = rsqrtf(var + 1e-5f);
    #pragma unroll
    for (int i = 0; i < 4; i++) { int c = tid + (i<<8); yr[c] = (sm[c]-mean)*rstd*g[c] + b[c]; }
}

// ---------------- softmax ----------------
__global__ void softmax_k(float* __restrict__ S, int L) {
    float* r = S + (size_t)blockIdx.x * L;
    int tid = threadIdx.x;
    __shared__ float red[256];
    int cnt = L >> 8;
    float v[8];
    float mx = -3.4e38f;
    for (int i = 0; i < cnt; i++) { v[i] = r[tid + (i<<8)]; mx = fmaxf(mx, v[i]); }
    red[tid] = mx; __syncthreads();
    for (int st = 128; st > 0; st >>= 1) { if (tid < st) red[tid] = fmaxf(red[tid], red[tid+st]); __syncthreads(); }
    mx = red[0]; __syncthreads();
    float sum = 0.f;
    for (int i = 0; i < cnt; i++) { v[i] = expf(v[i]-mx); sum += v[i]; }
    red[tid] = sum; __syncthreads();
    for (int st = 128; st > 0; st >>= 1) { if (tid < st) red[tid] += red[tid+st]; __syncthreads(); }
    float inv = 1.0f / red[0];
    for (int i = 0; i < cnt; i++) r[tid + (i<<8)] = v[i]*inv;
}

// ---------------- bf16 split helpers ----------------
// pack (x0,x1) into bf16x2 hi-word pair + bf16x2 lo-residual pair
__device__ __forceinline__ uint2 bfsplit2(float x0, float x1) {
    unsigned h;
    asm("cvt.rn.bf16x2.f32 %0, %1, %2;" : "=r"(h) : "f"(x1), "f"(x0)); // upper=x1, lower=x0
    float f0 = __uint_as_float(h << 16);
    float f1 = __uint_as_float(h & 0xFFFF0000u);
    unsigned l;
    asm("cvt.rn.bf16x2.f32 %0, %1, %2;" : "=r"(l) : "f"(x1 - f1), "f"(x0 - f0));
    return make_uint2(h, l);
}

__device__ __forceinline__ void mma16(float* c, const unsigned* a, const unsigned* b) {
    asm volatile("mma.sync.aligned.m16n8k16.row.col.f32.bf16.bf16.f32 "
        "{%0,%1,%2,%3},{%4,%5,%6,%7},{%8,%9},{%0,%1,%2,%3};"
        : "+f"(c[0]), "+f"(c[1]), "+f"(c[2]), "+f"(c[3])
        : "r"(a[0]), "r"(a[1]), "r"(a[2]), "r"(a[3]), "r"(b[0]), "r"(b[1]));
}

// A smem: [row 0..127][kpair 0..15] stride 20 (uint = bf16x2 along k)
// B smem BT:  [n 0..63][kpair 0..15] stride 20
// B smem !BT: [kpair 0..15][n 0..63] stride 72
#define ASTR 20
#define BSTR_BT 20
#define BSTR_NT 72

// one k16 MMA step (3-term bf16 split), shared by all GEMM kernels
template<bool BT>
__device__ __forceinline__ void mma_step16(
    float c[2][4][4],
    const unsigned* __restrict__ AsH, const unsigned* __restrict__ AsL,
    const unsigned* __restrict__ BsH, const unsigned* __restrict__ BsL,
    int wm, int wn, int g, int tig, int pb)
{
    unsigned ah[2][4], al[2][4];
    #pragma unroll
    for (int mt = 0; mt < 2; mt++) {
        int rb = wm + mt*16 + g;
        int i0 = rb*ASTR + pb + tig, i1 = (rb+8)*ASTR + pb + tig;
        ah[mt][0] = AsH[i0];   al[mt][0] = AsL[i0];
        ah[mt][1] = AsH[i1];   al[mt][1] = AsL[i1];
        ah[mt][2] = AsH[i0+4]; al[mt][2] = AsL[i0+4];
        ah[mt][3] = AsH[i1+4]; al[mt][3] = AsL[i1+4];
    }
    unsigned bh[4][2], bl[4][2];
    #pragma unroll
    for (int nt = 0; nt < 4; nt++) {
        int nb = wn + nt*8 + g;
        int j0, j1;
        if (BT) { j0 = nb*BSTR_BT + pb + tig; j1 = j0 + 4; }
        else    { j0 = (pb+tig)*BSTR_NT + nb; j1 = (pb+tig+4)*BSTR_NT + nb; }
        bh[nt][0] = BsH[j0]; bl[nt][0] = BsL[j0];
        bh[nt][1] = BsH[j1]; bl[nt][1] = BsL[j1];
    }
    #pragma unroll
    for (int mt = 0; mt < 2; mt++)
        #pragma unroll
        for (int nt = 0; nt < 4; nt++) {
            mma16(c[mt][nt], ah[mt], bh[nt]);
            mma16(c[mt][nt], ah[mt], bl[nt]);
            mma16(c[mt][nt], al[mt], bh[nt]);
        }
}

// ---------------- 3xBF16 GEMM, BK=32, block 128x64, 8 warps ----------------
// C[M,N] = alpha * A[M,K] * op(B) + bias + res
template<bool BT>
__global__ __launch_bounds__(256, 2) void mma_gemm(
    const float* __restrict__ A, int lda, long long sAo, long long sAi,
    const float* __restrict__ B, int ldb, long long sBo, long long sBi,
    float* __restrict__ C, int ldc, long long sCo, long long sCi,
    int M, int N, int K, int inner,
    const float* __restrict__ bias, float alpha, const float* __restrict__ res)
{
    int z = blockIdx.z;
    int zo = z / inner, zi = z - zo * inner;
    A += zo * sAo + zi * sAi;
    B += zo * sBo + zi * sBi;
    C += zo * sCo + zi * sCi;
    if (res) res += zo * sCo + zi * sCi;

    __shared__ unsigned AsH[128*ASTR], AsL[128*ASTR];
    __shared__ unsigned BsH[BT ? 64*BSTR_BT : 16*BSTR_NT];
    __shared__ unsigned BsL[BT ? 64*BSTR_BT : 16*BSTR_NT];

    int tid = threadIdx.x, lane = tid & 31, warp = tid >> 5;
    int g = lane >> 2, tig = lane & 3;
    int wm = (warp & 3) * 32, wn = (warp >> 2) * 32;
    int m0 = blockIdx.y * 128, n0 = blockIdx.x * 64;

    float c[2][4][4] = {};
    float4 aR[4], bR[2];

    int arA = tid >> 3, aqk = (tid & 7) << 2;            // A: rows arA+32i, k quad aqk
    int bn_ = tid >> 3, bqk = (tid & 7) << 2;            // BT B
    int kb  = (tid >> 4) << 1, n4 = (tid & 15) << 2;     // !BT B

    // prologue: load tile 0
    #pragma unroll
    for (int i = 0; i < 4; i++) {
        int gm = m0 + arA + i*32;
        aR[i] = (gm < M) ? *(const float4*)&A[(long long)gm * lda + aqk] : make_float4(0,0,0,0);
    }
    if (BT) {
        bR[0] = *(const float4*)&B[(long long)(n0 + bn_)      * ldb + bqk];
        bR[1] = *(const float4*)&B[(long long)(n0 + bn_ + 32) * ldb + bqk];
    } else {
        bR[0] = *(const float4*)&B[(long long)kb       * ldb + n0 + n4];
        bR[1] = *(const float4*)&B[(long long)(kb + 1) * ldb + n0 + n4];
    }

    for (int k0 = 0; k0 < K; k0 += 32) {
        // stage split bf16 tiles
        #pragma unroll
        for (int i = 0; i < 4; i++) {
            int base = (arA + i*32)*ASTR + (aqk >> 1);
            uint2 p0 = bfsplit2(aR[i].x, aR[i].y);
            uint2 p1 = bfsplit2(aR[i].z, aR[i].w);
            *(uint2*)&AsH[base] = make_uint2(p0.x, p1.x);
            *(uint2*)&AsL[base] = make_uint2(p0.y, p1.y);
        }
        if (BT) {
            #pragma unroll
            for (int i = 0; i < 2; i++) {
                int base = (bn_ + i*32)*BSTR_BT + (bqk >> 1);
                uint2 p0 = bfsplit2(i ? bR[1].x : bR[0].x, i ? bR[1].y : bR[0].y);
                uint2 p1 = bfsplit2(i ? bR[1].z : bR[0].z, i ? bR[1].w : bR[0].w);
                *(uint2*)&BsH[base] = make_uint2(p0.x, p1.x);
                *(uint2*)&BsL[base] = make_uint2(p0.y, p1.y);
            }
        } else {
            uint2 q0 = bfsplit2(bR[0].x, bR[1].x);
            uint2 q1 = bfsplit2(bR[0].y, bR[1].y);
            uint2 q2 = bfsplit2(bR[0].z, bR[1].z);
            uint2 q3 = bfsplit2(bR[0].w, bR[1].w);
            int base = (kb >> 1)*BSTR_NT + n4;
            *(uint4*)&BsH[base] = make_uint4(q0.x, q1.x, q2.x, q3.x);
            *(uint4*)&BsL[base] = make_uint4(q0.y, q1.y, q2.y, q3.y);
        }
        __syncthreads();

        // prefetch next tile
        int k1 = k0 + 32;
        if (k1 < K) {
            #pragma unroll
            for (int i = 0; i < 4; i++) {
                int gm = m0 + arA + i*32;
                aR[i] = (gm < M) ? *(const float4*)&A[(long long)gm * lda + k1 + aqk] : make_float4(0,0,0,0);
            }
            if (BT) {
                bR[0] = *(const float4*)&B[(long long)(n0 + bn_)      * ldb + k1 + bqk];
                bR[1] = *(const float4*)&B[(long long)(n0 + bn_ + 32) * ldb + k1 + bqk];
            } else {
                bR[0] = *(const float4*)&B[(long long)(k1 + kb)     * ldb + n0 + n4];
                bR[1] = *(const float4*)&B[(long long)(k1 + kb + 1) * ldb + n0 + n4];
            }
        }

        mma_step16<BT>(c, AsH, AsL, BsH, BsL, wm, wn, g, tig, 0);
        mma_step16<BT>(c, AsH, AsL, BsH, BsL, wm, wn, g, tig, 8);
        __syncthreads();
    }

    // ---- epilogue ----
    #pragma unroll
    for (int mt = 0; mt < 2; mt++) {
        int r0 = m0 + wm + mt*16 + g;
        #pragma unroll
        for (int nt = 0; nt < 4; nt++) {
            int col = n0 + wn + nt*8 + tig*2;
            float bv0 = bias ? bias[col]   : 0.f;
            float bv1 = bias ? bias[col+1] : 0.f;
            if (r0 < M) {
                float v0 = alpha*c[mt][nt][0] + bv0;
                float v1 = alpha*c[mt][nt][1] + bv1;
                if (res) { v0 += res[(long long)r0*ldc + col]; v1 += res[(long long)r0*ldc + col + 1]; }
                C[(long long)r0*ldc + col]     = v0;
                C[(long long)r0*ldc + col + 1] = v1;
            }
            int r1 = r0 + 8;
            if (r1 < M) {
                float v2 = alpha*c[mt][nt][2] + bv0;
                float v3 = alpha*c[mt][nt][3] + bv1;
                if (res) { v2 += res[(long long)r1*ldc + col]; v3 += res[(long long)r1*ldc + col + 1]; }
                C[(long long)r1*ldc + col]     = v2;
                C[(long long)r1*ldc + col + 1] = v3;
            }
        }
    }
}

// ---------------- JAX threefry2x32 / normal ----------------
__device__ __forceinline__ void threefry42(unsigned c0, unsigned c1, unsigned& o0, unsigned& o1) {
    const unsigned k0 = 0u, k1 = 42u;
    const unsigned k2 = 0x1BD11BDAu ^ k0 ^ k1;
    unsigned x0 = c0 + k0, x1 = c1 + k1;
#define TF_R(r) { x0 += x1; x1 = (x1 << r) | (x1 >> (32 - r)); x1 ^= x0; }
    TF_R(13) TF_R(15) TF_R(26) TF_R(6)   x0 += k1; x1 += k2 + 1u;
    TF_R(17) TF_R(29) TF_R(16) TF_R(24)  x0 += k2; x1 += k0 + 2u;
    TF_R(13) TF_R(15) TF_R(26) TF_R(6)   x0 += k0; x1 += k1 + 3u;
    TF_R(17) TF_R(29) TF_R(16) TF_R(24)  x0 += k1; x1 += k2 + 4u;
    TF_R(13) TF_R(15) TF_R(26) TF_R(6)   x0 += k2; x1 += k0 + 5u;
#undef TF_R
    o0 = x0; o1 = x1;
}

__device__ __forceinline__ float erfinv_f(float x) {
    float w = -log1pf(__fmul_rn(-x, x));
    float p;
    if (w < 5.0f) {
        w = __fadd_rn(w, -2.5f);
        p = 2.81022636e-08f;
        p = __fadd_rn(__fmul_rn(p, w),  3.43273939e-07f);
        p = __fadd_rn(__fmul_rn(p, w), -3.5233877e-06f);
        p = __fadd_rn(__fmul_rn(p, w), -4.39150654e-06f);
        p = __fadd_rn(__fmul_rn(p, w),  0.00021858087f);
        p = __fadd_rn(__fmul_rn(p, w), -0.00125372503f);
        p = __fadd_rn(__fmul_rn(p, w), -0.00417768164f);
        p = __fadd_rn(__fmul_rn(p, w),  0.246640727f);
        p = __fadd_rn(__fmul_rn(p, w),  1.50140941f);
    } else {
        w = __fadd_rn(sqrtf(w), -3.0f);
        p = -0.000200214257f;
        p = __fadd_rn(__fmul_rn(p, w),  0.000100950558f);
        p = __fadd_rn(__fmul_rn(p, w),  0.00134934322f);
        p = __fadd_rn(__fmul_rn(p, w), -0.00367342844f);
        p = __fadd_rn(__fmul_rn(p, w),  0.00573950773f);
        p = __fadd_rn(__fmul_rn(p, w), -0.0076224613f);
        p = __fadd_rn(__fmul_rn(p, w),  0.00943887047f);
        p = __fadd_rn(__fmul_rn(p, w),  1.00167406f);
        p = __fadd_rn(__fmul_rn(p, w),  2.83297682f);
    }
    return __fmul_rn(p, x);
}

// partitionable threefry: counter (0, i), bits = out0 ^ out1
__device__ __forceinline__ float jax_normal(int i) {
    unsigned o0, o1;
    threefry42(0u, (unsigned)i, o0, o1);
    unsigned bits = o0 ^ o1;
    unsigned fb = (bits >> 9) | 0x3f800000u;
    float u01 = __fadd_rn(__uint_as_float(fb), -1.0f);
    const float lo = -0.99999994f;
    float u = __fadd_rn(__fmul_rn(u01, 2.0f), lo);
    u = fmaxf(lo, u);
    return __fmul_rn(1.41421354f, erfinv_f(u));
}

// ---------------- MoE router ----------------
__global__ void zero_counts_k() { if (threadIdx.x < Ev) g_counts[threadIdx.x] = 0; }

__global__ void router_k(const float* __restrict__ xm,
                         const float* __restrict__ rw, const float* __restrict__ rb,
                         const float* __restrict__ nw, const float* __restrict__ nb) {
    int t = blockIdx.x;
    int tid = threadIdx.x;
    int w = tid >> 5, lane = tid & 31;
    __shared__ float sl[8], sn[8];
    const float* xr = xm + (long long)t * 1024;
    const float* rwe = rw + w * 1024;
    const float* nwe = nw + w * 1024;
    float sr = 0.f, s_n = 0.f;
    for (int d = lane; d < 1024; d += 32) {
        float xv = xr[d];
        sr  += xv * rwe[d];
        s_n += xv * nwe[d];
    }
    #pragma unroll
    for (int o = 16; o; o >>= 1) {
        sr  += __shfl_down_sync(0xffffffffu, sr, o);
        s_n += __shfl_down_sync(0xffffffffu, s_n, o);
    }
    if (lane == 0) { sl[w] = sr + rb[w]; sn[w] = s_n + nb[w]; }
    __syncthreads();
    if (tid == 0) {
        float noisy[8];
        #pragma unroll
        for (int e = 0; e < 8; e++) {
            float nrm = jax_normal(t * 8 + e);
            float zz = sn[e];
            float sp = fmaxf(zz, 0.f) + log1pf(expf(-fabsf(zz)));
            noisy[e] = sl[e] + nrm * sp;
        }
        int i1 = 0;
        #pragma unroll
        for (int e = 1; e < 8; e++) if (noisy[e] > noisy[i1]) i1 = e;
        int i2 = (i1 == 0) ? 1 : 0;
        #pragma unroll
        for (int e = 0; e < 8; e++) if (e != i1 && noisy[e] > noisy[i2]) i2 = e;
        float mx = noisy[i1];
        float e1 = expf(noisy[i1] - mx);
        float e2 = expf(noisy[i2] - mx);
        float Z  = e1 + e2;
        g_probs[2*t]   = e1 / Z;
        g_probs[2*t+1] = e2 / Z;
        int p1 = atomicAdd(&g_counts[i1], 1); g_elist[i1 * MAXTOK + p1] = 2*t;
        int p2 = atomicAdd(&g_counts[i2], 1); g_elist[i2 * MAXTOK + p2] = 2*t + 1;
    }
}

// ---------------- MoE bf16-split GEMMs (!BT layout) ----------------
__global__ __launch_bounds__(256, 2) void moe_mma1(const float* __restrict__ xm,
                                                   const float* __restrict__ w1,
                                                   const float* __restrict__ b1) {
    int e = blockIdx.z;
    int cnt = g_counts[e];
    int m0 = blockIdx.y * 128;
    if (m0 >= cnt) return;
    int n0 = blockIdx.x * 64;

    __shared__ int slots[128];
    __shared__ unsigned AsH[128*ASTR], AsL[128*ASTR];
    __shared__ unsigned BsH[16*BSTR_NT], BsL[16*BSTR_NT];

    int tid = threadIdx.x, lane = tid & 31, warp = tid >> 5;
    int g = lane >> 2, tig = lane & 3;
    int wm = (warp & 3) * 32, wn = (warp >> 2) * 32;
    if (tid < 128) slots[tid] = (m0 + tid < cnt) ? g_elist[e * MAXTOK + m0 + tid] : -1;
    __syncthreads();

    const float* Be = w1 + (long long)e * 1024 * 4096;
    float c[2][4][4] = {};
    float4 aR[4], bR[2];

    int arA = tid >> 3, aqk = (tid & 7) << 2;
    int kb  = (tid >> 4) << 1, n4 = (tid & 15) << 2;
    int sg[4];
    #pragma unroll
    for (int i = 0; i < 4; i++) sg[i] = slots[arA + i*32];

    #pragma unroll
    for (int i = 0; i < 4; i++)
        aR[i] = (sg[i] >= 0) ? *(const float4*)&xm[(long long)(sg[i] >> 1)*1024 + aqk] : make_float4(0,0,0,0);
    bR[0] = *(const float4*)&Be[(long long)kb       * 4096 + n0 + n4];
    bR[1] = *(const float4*)&Be[(long long)(kb + 1) * 4096 + n0 + n4];

    for (int k0 = 0; k0 < 1024; k0 += 32) {
        #pragma unroll
        for (int i = 0; i < 4; i++) {
            int base = (arA + i*32)*ASTR + (aqk >> 1);
            uint2 p0 = bfsplit2(aR[i].x, aR[i].y);
            uint2 p1 = bfsplit2(aR[i].z, aR[i].w);
            *(uint2*)&AsH[base] = make_uint2(p0.x, p1.x);
            *(uint2*)&AsL[base] = make_uint2(p0.y, p1.y);
        }
        {
            uint2 q0 = bfsplit2(bR[0].x, bR[1].x);
            uint2 q1 = bfsplit2(bR[0].y, bR[1].y);
            uint2 q2 = bfsplit2(bR[0].z, bR[1].z);
            uint2 q3 = bfsplit2(bR[0].w, bR[1].w);
            int base = (kb >> 1)*BSTR_NT + n4;
            *(uint4*)&BsH[base] = make_uint4(q0.x, q1.x, q2.x, q3.x);
            *(uint4*)&BsL[base] = make_uint4(q0.y, q1.y, q2.y, q3.y);
        }
        __syncthreads();
        int k1 = k0 + 32;
        if (k1 < 1024) {
            #pragma unroll
            for (int i = 0; i < 4; i++)
                aR[i] = (sg[i] >= 0) ? *(const float4*)&xm[(long long)(sg[i] >> 1)*1024 + k1 + aqk] : make_float4(0,0,0,0);
            bR[0] = *(const float4*)&Be[(long long)(k1 + kb)     * 4096 + n0 + n4];
            bR[1] = *(const float4*)&Be[(long long)(k1 + kb + 1) * 4096 + n0 + n4];
        }
        mma_step16<false>(c, AsH, AsL, BsH, BsL, wm, wn, g, tig, 0);
        mma_step16<false>(c, AsH, AsL, BsH, BsL, wm, wn, g, tig, 8);
        __syncthreads();
    }

    #pragma unroll
    for (int mt = 0; mt < 2; mt++) {
        int lr0 = wm + mt*16 + g;
        int s0 = slots[lr0], s1 = slots[lr0 + 8];
        #pragma unroll
        for (int nt = 0; nt < 4; nt++) {
            int col = n0 + wn + nt*8 + tig*2;
            float bv0 = b1[e*4096 + col], bv1 = b1[e*4096 + col + 1];
            if (s0 >= 0) {
                float v0 = c[mt][nt][0] + bv0;
                float v1 = c[mt][nt][1] + bv1;
                v0 = 0.5f * v0 * (1.0f + erff(v0 * 0.70710677f));
                v1 = 0.5f * v1 * (1.0f + erff(v1 * 0.70710677f));
                g_h[(long long)s0*4096 + col]     = v0;
                g_h[(long long)s0*4096 + col + 1] = v1;
            }
            if (s1 >= 0) {
                float v2 = c[mt][nt][2] + bv0;
                float v3 = c[mt][nt][3] + bv1;
                v2 = 0.5f * v2 * (1.0f + erff(v2 * 0.70710677f));
                v3 = 0.5f * v3 * (1.0f + erff(v3 * 0.70710677f));
                g_h[(long long)s1*4096 + col]     = v2;
                g_h[(long long)s1*4096 + col + 1] = v3;
            }
        }
    }
}

__global__ __launch_bounds__(256, 2) void moe_mma2(const float* __restrict__ w2,
                                                   const float* __restrict__ b2) {
    int e = blockIdx.z;
    int cnt = g_counts[e];
    int m0 = blockIdx.y * 128;
    if (m0 >= cnt) return;
    int n0 = blockIdx.x * 64;

    __shared__ int slots[128];
    __shared__ unsigned AsH[128*ASTR], AsL[128*ASTR];
    __shared__ unsigned BsH[16*BSTR_NT], BsL[16*BSTR_NT];

    int tid = threadIdx.x, lane = tid & 31, warp = tid >> 5;
    int g = lane >> 2, tig = lane & 3;
    int wm = (warp & 3) * 32, wn = (warp >> 2) * 32;
    if (tid < 128) slots[tid] = (m0 + tid < cnt) ? g_elist[e * MAXTOK + m0 + tid] : -1;
    __syncthreads();

    const float* Be = w2 + (long long)e * 4096 * 1024;
    float c[2][4][4] = {};
    float4 aR[4], bR[2];

    int arA = tid >> 3, aqk = (tid & 7) << 2;
    int kb  = (tid >> 4) << 1, n4 = (tid & 15) << 2;
    int sg[4];
    #pragma unroll
    for (int i = 0; i < 4; i++) sg[i] = slots[arA + i*32];

    #pragma unroll
    for (int i = 0; i < 4; i++)
        aR[i] = (sg[i] >= 0) ? *(const float4*)&g_h[(long long)sg[i]*4096 + aqk] : make_float4(0,0,0,0);
    bR[0] = *(const float4*)&Be[(long long)kb       * 1024 + n0 + n4];
    bR[1] = *(const float4*)&Be[(long long)(kb + 1) * 1024 + n0 + n4];

    for (int k0 = 0; k0 < 4096; k0 += 32) {
        #pragma unroll
        for (int i = 0; i < 4; i++) {
            int base = (arA + i*32)*ASTR + (aqk >> 1);
            uint2 p0 = bfsplit2(aR[i].x, aR[i].y);
            uint2 p1 = bfsplit2(aR[i].z, aR[i].w);
            *(uint2*)&AsH[base] = make_uint2(p0.x, p1.x);
            *(uint2*)&AsL[base] = make_uint2(p0.y, p1.y);
        }
        {
            uint2 q0 = bfsplit2(bR[0].x, bR[1].x);
            uint2 q1 = bfsplit2(bR[0].y, bR[1].y);
            uint2 q2 = bfsplit2(bR[0].z, bR[1].z);
            uint2 q3 = bfsplit2(bR[0].w, bR[1].w);
            int base = (kb >> 1)*BSTR_NT + n4;
            *(uint4*)&BsH[base] = make_uint4(q0.x, q1.x, q2.x, q3.x);
            *(uint4*)&BsL[base] = make_uint4(q0.y, q1.y, q2.y, q3.y);
        }
        __syncthreads();
        int k1 = k0 + 32;
        if (k1 < 4096) {
            #pragma unroll
            for (int i = 0; i < 4; i++)
                aR[i] = (sg[i] >= 0) ? *(const float4*)&g_h[(long long)sg[i]*4096 + k1 + aqk] : make_float4(0,0,0,0);
            bR[0] = *(const float4*)&Be[(long long)(k1 + kb)     * 1024 + n0 + n4];
            bR[1] = *(const float4*)&Be[(long long)(k1 + kb + 1) * 1024 + n0 + n4];
        }
        mma_step16<false>(c, AsH, AsL, BsH, BsL, wm, wn, g, tig, 0);
        mma_step16<false>(c, AsH, AsL, BsH, BsL, wm, wn, g, tig, 8);
        __syncthreads();
    }

    #pragma unroll
    for (int mt = 0; mt < 2; mt++) {
        int lr0 = wm + mt*16 + g;
        int s0 = slots[lr0], s1 = slots[lr0 + 8];
        #pragma unroll
        for (int nt = 0; nt < 4; nt++) {
            int col = n0 + wn + nt*8 + tig*2;
            float bv0 = b2[e*1024 + col], bv1 = b2[e*1024 + col + 1];
            if (s0 >= 0) {
                g_eo[(long long)s0*1024 + col]     = c[mt][nt][0] + bv0;
                g_eo[(long long)s0*1024 + col + 1] = c[mt][nt][1] + bv1;
            }
            if (s1 >= 0) {
                g_eo[(long long)s1*1024 + col]     = c[mt][nt][2] + bv0;
                g_eo[(long long)s1*1024 + col + 1] = c[mt][nt][3] + bv1;
            }
        }
    }
}

__global__ void combine_k(const float* __restrict__ x, float* __restrict__ out) {
    int idx = blockIdx.x * 256 + threadIdx.x;
    int t = idx >> 10, d = idx & 1023;
    float v = x[idx];
    v += g_probs[2*t]     * g_eo[(long long)(2*t)     * 1024 + d];
    v += g_probs[2*t + 1] * g_eo[(long long)(2*t + 1) * 1024 + d];
    out[idx] = v;
}

// ---------------- launcher ----------------
extern "C" void kernel_launch(void* const* d_in, const int* in_sizes, int n_in,
                              void* d_out, int out_size) {
    const float* q        = (const float*)d_in[0];
    const float* kv       = (const float*)d_in[1];
    const float* ln_cq_g  = (const float*)d_in[2];
    const float* ln_cq_b  = (const float*)d_in[3];
    const float* ln_ckv_g = (const float*)d_in[4];
    const float* ln_ckv_b = (const float*)d_in[5];
    const float* ln_s_g   = (const float*)d_in[6];
    const float* ln_s_b   = (const float*)d_in[7];
    const float* ln_m_g   = (const float*)d_in[8];
    const float* ln_m_b   = (const float*)d_in[9];
    const float* ca_in_w  = (const float*)d_in[10];
    const float* ca_in_b  = (const float*)d_in[11];
    const float* ca_out_w = (const float*)d_in[12];
    const float* ca_out_b = (const float*)d_in[13];
    const float* sa_in_w  = (const float*)d_in[14];
    const float* sa_in_b  = (const float*)d_in[15];
    const float* sa_out_w = (const float*)d_in[16];
    const float* sa_out_b = (const float*)d_in[17];
    const float* moe_rw   = (const float*)d_in[18];
    const float* moe_rb   = (const float*)d_in[19];
    const float* moe_nw   = (const float*)d_in[20];
    const float* moe_nb   = (const float*)d_in[21];
    const float* moe_w1   = (const float*)d_in[22];
    const float* moe_b1   = (const float*)d_in[23];
    const float* moe_w2   = (const float*)d_in[24];
    const float* moe_b2   = (const float*)d_in[25];
    float* out = (float*)d_out;

    float *p_x, *p_ln1, *p_lnkv, *p_qp, *p_kvp, *p_scores, *p_ao;
    cudaGetSymbolAddress((void**)&p_x,      g_x);
    cudaGetSymbolAddress((void**)&p_ln1,    g_ln1);
    cudaGetSymbolAddress((void**)&p_lnkv,   g_lnkv);
    cudaGetSymbolAddress((void**)&p_qp,     g_qp);
    cudaGetSymbolAddress((void**)&p_kvp,    g_kvp);
    cudaGetSymbolAddress((void**)&p_scores, g_scores);
    cudaGetSymbolAddress((void**)&p_ao,     g_ao);

    const long long ZL = 0;

    // ===== Cross-attention =====
    ln_k<<<TQ, 256>>>(q,  p_ln1,  ln_cq_g,  ln_cq_b);
    ln_k<<<TKV, 256>>>(kv, p_lnkv, ln_ckv_g, ln_ckv_b);

    mma_gemm<true><<<dim3(16, 16, 1), 256>>>(p_ln1, 1024, ZL, ZL,
        ca_in_w, 1024, ZL, ZL, p_qp, 1024, ZL, ZL,
        TQ, 1024, 1024, 1, ca_in_b, 1.0f, nullptr);
    mma_gemm<true><<<dim3(32, 32, 1), 256>>>(p_lnkv, 1024, ZL, ZL,
        ca_in_w + 1024*1024, 1024, ZL, ZL, p_kvp, 2048, ZL, ZL,
        TKV, 2048, 1024, 1, ca_in_b + 1024, 1.0f, nullptr);
    mma_gemm<true><<<dim3(32, 8, 32), 256>>>(
        p_qp, 1024, (long long)NQv*1024, 64,
        p_kvp, 2048, (long long)NKVv*2048, 64,
        p_scores, 2048, (long long)Hv*NQv*NKVv, (long long)NQv*NKVv,
        1024, 2048, 64, 16, nullptr, 0.125f, nullptr);
    softmax_k<<<Bv*Hv*NQv, 256>>>(p_scores, 2048);
    mma_gemm<false><<<dim3(1, 8, 32), 256>>>(
        p_scores, 2048, (long long)Hv*NQv*NKVv, (long long)NQv*NKVv,
        p_kvp + 1024, 2048, (long long)NKVv*2048, 64,
        p_ao, 1024, (long long)NQv*1024, 64,
        1024, 64, 2048, 16, nullptr, 1.0f, nullptr);
    mma_gemm<true><<<dim3(16, 16, 1), 256>>>(p_ao, 1024, ZL, ZL,
        ca_out_w, 1024, ZL, ZL, p_x, 1024, ZL, ZL,
        TQ, 1024, 1024, 1, ca_out_b, 1.0f, q);

    // ===== Self-attention =====
    ln_k<<<TQ, 256>>>(p_x, p_ln1, ln_s_g, ln_s_b);
    mma_gemm<true><<<dim3(48, 16, 1), 256>>>(p_ln1, 1024, ZL, ZL,
        sa_in_w, 1024, ZL, ZL, p_kvp, 3072, ZL, ZL,
        TQ, 3072, 1024, 1, sa_in_b, 1.0f, nullptr);
    mma_gemm<true><<<dim3(16, 8, 32), 256>>>(
        p_kvp, 3072, (long long)NQv*3072, 64,
        p_kvp + 1024, 3072, (long long)NQv*3072, 64,
        p_scores, 1024, (long long)Hv*NQv*NQv, (long long)NQv*NQv,
        1024, 1024, 64, 16, nullptr, 0.125f, nullptr);
    softmax_k<<<Bv*Hv*NQv, 256>>>(p_scores, 1024);
    mma_gemm<false><<<dim3(1, 8, 32), 256>>>(
        p_scores, 1024, (long long)Hv*NQv*NQv, (long long)NQv*NQv,
        p_kvp + 2048, 3072, (long long)NQv*3072, 64,
        p_ao, 1024, (long long)NQv*1024, 64,
        1024, 64, 1024, 16, nullptr, 1.0f, nullptr);
    mma_gemm<true><<<dim3(16, 16, 1), 256>>>(p_ao, 1024, ZL, ZL,
        sa_out_w, 1024, ZL, ZL, p_x, 1024, ZL, ZL,
        TQ, 1024, 1024, 1, sa_out_b, 1.0f, p_x);

    // ===== MoE =====
    ln_k<<<TQ, 256>>>(p_x, p_ln1, ln_m_g, ln_m_b);
    zero_counts_k<<<1, 32>>>();
    router_k<<<TQ, 256>>>(p_ln1, moe_rw, moe_rb, moe_nw, moe_nb);
    moe_mma1<<<dim3(64, 16, 8), 256>>>(p_ln1, moe_w1, moe_b1);
    moe_mma2<<<dim3(16, 16, 8), 256>>>(moe_w2, moe_b2);
    combine_k<<<(TQ*Dv)/256, 256>>>(p_x, out);
}

// round 8
// speedup vs baseline: 2.3918x; 1.1107x over previous
#include <cuda_runtime.h>
#include <cuda_bf16.h>
#include <math.h>
#include <stdint.h>

// Problem dims
#define Bv    2
#define NQv   1024
#define NKVv  2048
#define Dv    1024
#define Hv    16
#define DHv   64
#define Ev    8
#define FFv   4096
#define TQ    (Bv*NQv)
#define TKV   (Bv*NKVv)
#define MAXTOK 2048

// ---------------- scratch ----------------
__device__ float g_x[TQ*Dv];
__device__ float g_ln1[TQ*Dv];
__device__ float g_lnkv[TKV*Dv];
__device__ float g_qp[TQ*Dv];
__device__ float g_kvp[TKV*2048];
__device__ float g_scores[(size_t)Bv*Hv*NQv*NKVv];
__device__ float g_ao[TQ*Dv];
__device__ float g_h[(size_t)TQ*2*FFv];
__device__ float g_eo[(size_t)TQ*2*Dv];
__device__ float g_probs[TQ*2];
__device__ int   g_counts[Ev];
__device__ int   g_elist[Ev*MAXTOK];

// ---------------- layernorm ----------------
__global__ void ln_k(const float* __restrict__ x, float* __restrict__ y,
                     const float* __restrict__ g, const float* __restrict__ b) {
    long row = blockIdx.x;
    const float* xr = x + row * 1024;
    float* yr = y + row * 1024;
    __shared__ float sm[1024];
    __shared__ float red[256];
    int tid = threadIdx.x;
    float s = 0.f;
    #pragma unroll
    for (int i = 0; i < 4; i++) { float v = xr[tid + (i<<8)]; sm[tid + (i<<8)] = v; s += v; }
    red[tid] = s; __syncthreads();
    for (int st = 128; st > 0; st >>= 1) { if (tid < st) red[tid] += red[tid + st]; __syncthreads(); }
    float mean = red[0] * (1.0f/1024.0f); __syncthreads();
    float s2 = 0.f;
    #pragma unroll
    for (int i = 0; i < 4; i++) { float d = sm[tid + (i<<8)] - mean; s2 += d*d; }
    red[tid] = s2; __syncthreads();
    for (int st = 128; st > 0; st >>= 1) { if (tid < st) red[tid] += red[tid + st]; __syncthreads(); }
    float var = red[0] * (1.0f/1024.0f);
    float rstd = rsqrtf(var + 1e-5f);
    #pragma unroll
    for (int i = 0; i < 4; i++) { int c = tid + (i<<8); yr[c] = (sm[c]-mean)*rstd*g[c] + b[c]; }
}

// ---------------- softmax ----------------
__global__ void softmax_k(float* __restrict__ S, int L) {
    float* r = S + (size_t)blockIdx.x * L;
    int tid = threadIdx.x;
    __shared__ float red[256];
    int cnt = L >> 8;
    float v[8];
    float mx = -3.4e38f;
    for (int i = 0; i < cnt; i++) { v[i] = r[tid + (i<<8)]; mx = fmaxf(mx, v[i]); }
    red[tid] = mx; __syncthreads();
    for (int st = 128; st > 0; st >>= 1) { if (tid < st) red[tid] = fmaxf(red[tid], red[tid+st]); __syncthreads(); }
    mx = red[0]; __syncthreads();
    float sum = 0.f;
    for (int i = 0; i < cnt; i++) { v[i] = expf(v[i]-mx); sum += v[i]; }
    red[tid] = sum; __syncthreads();
    for (int st = 128; st > 0; st >>= 1) { if (tid < st) red[tid] += red[tid+st]; __syncthreads(); }
    float inv = 1.0f / red[0];
    for (int i = 0; i < cnt; i++) r[tid + (i<<8)] = v[i]*inv;
}

// ---------------- bf16 split helpers ----------------
__device__ __forceinline__ uint2 bfsplit2(float x0, float x1) {
    unsigned h;
    asm("cvt.rn.bf16x2.f32 %0, %1, %2;" : "=r"(h) : "f"(x1), "f"(x0)); // upper=x1, lower=x0
    float f0 = __uint_as_float(h << 16);
    float f1 = __uint_as_float(h & 0xFFFF0000u);
    unsigned l;
    asm("cvt.rn.bf16x2.f32 %0, %1, %2;" : "=r"(l) : "f"(x1 - f1), "f"(x0 - f0));
    return make_uint2(h, l);
}

__device__ __forceinline__ void mma16(float* c, const unsigned* a, const unsigned* b) {
    asm volatile("mma.sync.aligned.m16n8k16.row.col.f32.bf16.bf16.f32 "
        "{%0,%1,%2,%3},{%4,%5,%6,%7},{%8,%9},{%0,%1,%2,%3};"
        : "+f"(c[0]), "+f"(c[1]), "+f"(c[2]), "+f"(c[3])
        : "r"(a[0]), "r"(a[1]), "r"(a[2]), "r"(a[3]), "r"(b[0]), "r"(b[1]));
}

__device__ __forceinline__ void ldsm4(const unsigned* p, unsigned* r) {
    unsigned addr = (unsigned)__cvta_generic_to_shared(p);
    asm volatile("ldmatrix.sync.aligned.m8n8.x4.shared.b16 {%0,%1,%2,%3}, [%4];"
        : "=r"(r[0]), "=r"(r[1]), "=r"(r[2]), "=r"(r[3]) : "r"(addr));
}

// Unified smem layout (both operands K-major bf16x2 pairs):
// A: [row 0..127][kpair 0..15] stride 20 words
// B: [n   0..63 ][kpair 0..15] stride 20 words
#define ASTR 20

// one k16 MMA step via ldmatrix: 8 LDSM + 24 MMA per warp
__device__ __forceinline__ void mma_step_ldsm(
    float c[2][4][4],
    const unsigned* __restrict__ AsH, const unsigned* __restrict__ AsL,
    const unsigned* __restrict__ BsH, const unsigned* __restrict__ BsL,
    int aoff, int boff, int pb)
{
    unsigned ah0[4], al0[4], ah1[4], al1[4];
    ldsm4(AsH + aoff + pb,       ah0);
    ldsm4(AsL + aoff + pb,       al0);
    ldsm4(AsH + aoff + 320 + pb, ah1);
    ldsm4(AsL + aoff + 320 + pb, al1);
    unsigned bh01[4], bl01[4], bh23[4], bl23[4];
    ldsm4(BsH + boff + pb,       bh01);
    ldsm4(BsL + boff + pb,       bl01);
    ldsm4(BsH + boff + 320 + pb, bh23);
    ldsm4(BsL + boff + 320 + pb, bl23);

    #pragma unroll
    for (int mt = 0; mt < 2; mt++) {
        const unsigned* A_h = mt ? ah1 : ah0;
        const unsigned* A_l = mt ? al1 : al0;
        #pragma unroll
        for (int nt = 0; nt < 4; nt++) {
            const unsigned* B_h = (nt < 2 ? bh01 : bh23) + (nt & 1) * 2;
            const unsigned* B_l = (nt < 2 ? bl01 : bl23) + (nt & 1) * 2;
            mma16(c[mt][nt], A_h, B_h);
            mma16(c[mt][nt], A_h, B_l);
            mma16(c[mt][nt], A_l, B_h);
        }
    }
}

// per-thread loop-invariant ldmatrix offsets
__device__ __forceinline__ int a_ldsm_off(int wm, int lane) {
    return (wm + (lane & 15)) * ASTR + (lane >> 4) * 4;
}
__device__ __forceinline__ int b_ldsm_off(int wn, int lane) {
    return (wn + ((lane >> 4) << 3) + (lane & 7)) * ASTR + ((lane >> 3) & 1) * 4;
}

// ---------------- 3xBF16 GEMM, BK=32, block 128x64, 8 warps, ldmatrix ----------------
// C[M,N] = alpha * A[M,K] * op(B) + bias + res
// BT=true : B is [N,K] row-major;  BT=false: B is [K,N] row-major (staged transposed)
template<bool BT>
__global__ __launch_bounds__(256, 2) void mma_gemm(
    const float* __restrict__ A, int lda, long long sAo, long long sAi,
    const float* __restrict__ B, int ldb, long long sBo, long long sBi,
    float* __restrict__ C, int ldc, long long sCo, long long sCi,
    int M, int N, int K, int inner,
    const float* __restrict__ bias, float alpha, const float* __restrict__ res)
{
    int z = blockIdx.z;
    int zo = z / inner, zi = z - zo * inner;
    A += zo * sAo + zi * sAi;
    B += zo * sBo + zi * sBi;
    C += zo * sCo + zi * sCi;
    if (res) res += zo * sCo + zi * sCi;

    __shared__ unsigned AsH[128*ASTR], AsL[128*ASTR];
    __shared__ unsigned BsH[64*ASTR],  BsL[64*ASTR];

    int tid = threadIdx.x, lane = tid & 31, warp = tid >> 5;
    int g = lane >> 2, tig = lane & 3;
    int wm = (warp & 3) * 32, wn = (warp >> 2) * 32;
    int m0 = blockIdx.y * 128, n0 = blockIdx.x * 64;

    int aoff = a_ldsm_off(wm, lane);
    int boff = b_ldsm_off(wn, lane);

    float c[2][4][4] = {};
    float4 aR[4];
    float4 bRt[2];   // BT path
    float  bf[8];    // !BT path

    int arA = tid >> 3, aqk = (tid & 7) << 2;            // A rows arA+32i, k quad aqk
    int bn_ = tid >> 3, bqk = (tid & 7) << 2;            // BT B
    int bnc = tid & 63, bkg = tid >> 6;                  // !BT B: column bnc, k-group bkg

    // prologue: load tile 0
    #pragma unroll
    for (int i = 0; i < 4; i++) {
        int gm = m0 + arA + i*32;
        aR[i] = (gm < M) ? *(const float4*)&A[(long long)gm * lda + aqk] : make_float4(0,0,0,0);
    }
    if (BT) {
        bRt[0] = *(const float4*)&B[(long long)(n0 + bn_)      * ldb + bqk];
        bRt[1] = *(const float4*)&B[(long long)(n0 + bn_ + 32) * ldb + bqk];
    } else {
        #pragma unroll
        for (int j = 0; j < 8; j++)
            bf[j] = B[(long long)(bkg*8 + j) * ldb + n0 + bnc];
    }

    for (int k0 = 0; k0 < K; k0 += 32) {
        // ---- stage split bf16 tiles ----
        #pragma unroll
        for (int i = 0; i < 4; i++) {
            int base = (arA + i*32)*ASTR + (aqk >> 1);
            uint2 p0 = bfsplit2(aR[i].x, aR[i].y);
            uint2 p1 = bfsplit2(aR[i].z, aR[i].w);
            *(uint2*)&AsH[base] = make_uint2(p0.x, p1.x);
            *(uint2*)&AsL[base] = make_uint2(p0.y, p1.y);
        }
        if (BT) {
            #pragma unroll
            for (int i = 0; i < 2; i++) {
                int base = (bn_ + i*32)*ASTR + (bqk >> 1);
                uint2 p0 = bfsplit2(i ? bRt[1].x : bRt[0].x, i ? bRt[1].y : bRt[0].y);
                uint2 p1 = bfsplit2(i ? bRt[1].z : bRt[0].z, i ? bRt[1].w : bRt[0].w);
                *(uint2*)&BsH[base] = make_uint2(p0.x, p1.x);
                *(uint2*)&BsL[base] = make_uint2(p0.y, p1.y);
            }
        } else {
            uint2 q0 = bfsplit2(bf[0], bf[1]);
            uint2 q1 = bfsplit2(bf[2], bf[3]);
            uint2 q2 = bfsplit2(bf[4], bf[5]);
            uint2 q3 = bfsplit2(bf[6], bf[7]);
            int base = bnc*ASTR + bkg*4;
            *(uint4*)&BsH[base] = make_uint4(q0.x, q1.x, q2.x, q3.x);
            *(uint4*)&BsL[base] = make_uint4(q0.y, q1.y, q2.y, q3.y);
        }
        __syncthreads();

        // ---- prefetch next tile ----
        int k1 = k0 + 32;
        if (k1 < K) {
            #pragma unroll
            for (int i = 0; i < 4; i++) {
                int gm = m0 + arA + i*32;
                aR[i] = (gm < M) ? *(const float4*)&A[(long long)gm * lda + k1 + aqk] : make_float4(0,0,0,0);
            }
            if (BT) {
                bRt[0] = *(const float4*)&B[(long long)(n0 + bn_)      * ldb + k1 + bqk];
                bRt[1] = *(const float4*)&B[(long long)(n0 + bn_ + 32) * ldb + k1 + bqk];
            } else {
                #pragma unroll
                for (int j = 0; j < 8; j++)
                    bf[j] = B[(long long)(k1 + bkg*8 + j) * ldb + n0 + bnc];
            }
        }

        mma_step_ldsm(c, AsH, AsL, BsH, BsL, aoff, boff, 0);
        mma_step_ldsm(c, AsH, AsL, BsH, BsL, aoff, boff, 8);
        __syncthreads();
    }

    // ---- epilogue ----
    #pragma unroll
    for (int mt = 0; mt < 2; mt++) {
        int r0 = m0 + wm + mt*16 + g;
        #pragma unroll
        for (int nt = 0; nt < 4; nt++) {
            int col = n0 + wn + nt*8 + tig*2;
            float bv0 = bias ? bias[col]   : 0.f;
            float bv1 = bias ? bias[col+1] : 0.f;
            if (r0 < M) {
                float v0 = alpha*c[mt][nt][0] + bv0;
                float v1 = alpha*c[mt][nt][1] + bv1;
                if (res) { v0 += res[(long long)r0*ldc + col]; v1 += res[(long long)r0*ldc + col + 1]; }
                C[(long long)r0*ldc + col]     = v0;
                C[(long long)r0*ldc + col + 1] = v1;
            }
            int r1 = r0 + 8;
            if (r1 < M) {
                float v2 = alpha*c[mt][nt][2] + bv0;
                float v3 = alpha*c[mt][nt][3] + bv1;
                if (res) { v2 += res[(long long)r1*ldc + col]; v3 += res[(long long)r1*ldc + col + 1]; }
                C[(long long)r1*ldc + col]     = v2;
                C[(long long)r1*ldc + col + 1] = v3;
            }
        }
    }
}

// ---------------- JAX threefry2x32 / normal ----------------
__device__ __forceinline__ void threefry42(unsigned c0, unsigned c1, unsigned& o0, unsigned& o1) {
    const unsigned k0 = 0u, k1 = 42u;
    const unsigned k2 = 0x1BD11BDAu ^ k0 ^ k1;
    unsigned x0 = c0 + k0, x1 = c1 + k1;
#define TF_R(r) { x0 += x1; x1 = (x1 << r) | (x1 >> (32 - r)); x1 ^= x0; }
    TF_R(13) TF_R(15) TF_R(26) TF_R(6)   x0 += k1; x1 += k2 + 1u;
    TF_R(17) TF_R(29) TF_R(16) TF_R(24)  x0 += k2; x1 += k0 + 2u;
    TF_R(13) TF_R(15) TF_R(26) TF_R(6)   x0 += k0; x1 += k1 + 3u;
    TF_R(17) TF_R(29) TF_R(16) TF_R(24)  x0 += k1; x1 += k2 + 4u;
    TF_R(13) TF_R(15) TF_R(26) TF_R(6)   x0 += k2; x1 += k0 + 5u;
#undef TF_R
    o0 = x0; o1 = x1;
}

__device__ __forceinline__ float erfinv_f(float x) {
    float w = -log1pf(__fmul_rn(-x, x));
    float p;
    if (w < 5.0f) {
        w = __fadd_rn(w, -2.5f);
        p = 2.81022636e-08f;
        p = __fadd_rn(__fmul_rn(p, w),  3.43273939e-07f);
        p = __fadd_rn(__fmul_rn(p, w), -3.5233877e-06f);
        p = __fadd_rn(__fmul_rn(p, w), -4.39150654e-06f);
        p = __fadd_rn(__fmul_rn(p, w),  0.00021858087f);
        p = __fadd_rn(__fmul_rn(p, w), -0.00125372503f);
        p = __fadd_rn(__fmul_rn(p, w), -0.00417768164f);
        p = __fadd_rn(__fmul_rn(p, w),  0.246640727f);
        p = __fadd_rn(__fmul_rn(p, w),  1.50140941f);
    } else {
        w = __fadd_rn(sqrtf(w), -3.0f);
        p = -0.000200214257f;
        p = __fadd_rn(__fmul_rn(p, w),  0.000100950558f);
        p = __fadd_rn(__fmul_rn(p, w),  0.00134934322f);
        p = __fadd_rn(__fmul_rn(p, w), -0.00367342844f);
        p = __fadd_rn(__fmul_rn(p, w),  0.00573950773f);
        p = __fadd_rn(__fmul_rn(p, w), -0.0076224613f);
        p = __fadd_rn(__fmul_rn(p, w),  0.00943887047f);
        p = __fadd_rn(__fmul_rn(p, w),  1.00167406f);
        p = __fadd_rn(__fmul_rn(p, w),  2.83297682f);
    }
    return __fmul_rn(p, x);
}

// partitionable threefry: counter (0, i), bits = out0 ^ out1
__device__ __forceinline__ float jax_normal(int i) {
    unsigned o0, o1;
    threefry42(0u, (unsigned)i, o0, o1);
    unsigned bits = o0 ^ o1;
    unsigned fb = (bits >> 9) | 0x3f800000u;
    float u01 = __fadd_rn(__uint_as_float(fb), -1.0f);
    const float lo = -0.99999994f;
    float u = __fadd_rn(__fmul_rn(u01, 2.0f), lo);
    u = fmaxf(lo, u);
    return __fmul_rn(1.41421354f, erfinv_f(u));
}

// ---------------- MoE router ----------------
__global__ void zero_counts_k() { if (threadIdx.x < Ev) g_counts[threadIdx.x] = 0; }

__global__ void router_k(const float* __restrict__ xm,
                         const float* __restrict__ rw, const float* __restrict__ rb,
                         const float* __restrict__ nw, const float* __restrict__ nb) {
    int t = blockIdx.x;
    int tid = threadIdx.x;
    int w = tid >> 5, lane = tid & 31;
    __shared__ float sl[8], sn[8];
    const float* xr = xm + (long long)t * 1024;
    const float* rwe = rw + w * 1024;
    const float* nwe = nw + w * 1024;
    float sr = 0.f, s_n = 0.f;
    for (int d = lane; d < 1024; d += 32) {
        float xv = xr[d];
        sr  += xv * rwe[d];
        s_n += xv * nwe[d];
    }
    #pragma unroll
    for (int o = 16; o; o >>= 1) {
        sr  += __shfl_down_sync(0xffffffffu, sr, o);
        s_n += __shfl_down_sync(0xffffffffu, s_n, o);
    }
    if (lane == 0) { sl[w] = sr + rb[w]; sn[w] = s_n + nb[w]; }
    __syncthreads();
    if (tid == 0) {
        float noisy[8];
        #pragma unroll
        for (int e = 0; e < 8; e++) {
            float nrm = jax_normal(t * 8 + e);
            float zz = sn[e];
            float sp = fmaxf(zz, 0.f) + log1pf(expf(-fabsf(zz)));
            noisy[e] = sl[e] + nrm * sp;
        }
        int i1 = 0;
        #pragma unroll
        for (int e = 1; e < 8; e++) if (noisy[e] > noisy[i1]) i1 = e;
        int i2 = (i1 == 0) ? 1 : 0;
        #pragma unroll
        for (int e = 0; e < 8; e++) if (e != i1 && noisy[e] > noisy[i2]) i2 = e;
        float mx = noisy[i1];
        float e1 = expf(noisy[i1] - mx);
        float e2 = expf(noisy[i2] - mx);
        float Z  = e1 + e2;
        g_probs[2*t]   = e1 / Z;
        g_probs[2*t+1] = e2 / Z;
        int p1 = atomicAdd(&g_counts[i1], 1); g_elist[i1 * MAXTOK + p1] = 2*t;
        int p2 = atomicAdd(&g_counts[i2], 1); g_elist[i2 * MAXTOK + p2] = 2*t + 1;
    }
}

// ---------------- MoE bf16-split GEMMs (ldmatrix, transposed B staging) ----------------
__global__ __launch_bounds__(256, 2) void moe_mma1(const float* __restrict__ xm,
                                                   const float* __restrict__ w1,
                                                   const float* __restrict__ b1) {
    int e = blockIdx.z;
    int cnt = g_counts[e];
    int m0 = blockIdx.y * 128;
    if (m0 >= cnt) return;
    int n0 = blockIdx.x * 64;

    __shared__ int slots[128];
    __shared__ unsigned AsH[128*ASTR], AsL[128*ASTR];
    __shared__ unsigned BsH[64*ASTR],  BsL[64*ASTR];

    int tid = threadIdx.x, lane = tid & 31, warp = tid >> 5;
    int g = lane >> 2, tig = lane & 3;
    int wm = (warp & 3) * 32, wn = (warp >> 2) * 32;
    if (tid < 128) slots[tid] = (m0 + tid < cnt) ? g_elist[e * MAXTOK + m0 + tid] : -1;
    __syncthreads();

    int aoff = a_ldsm_off(wm, lane);
    int boff = b_ldsm_off(wn, lane);

    const float* Be = w1 + (long long)e * 1024 * 4096;
    float c[2][4][4] = {};
    float4 aR[4];
    float  bf[8];

    int arA = tid >> 3, aqk = (tid & 7) << 2;
    int bnc = tid & 63, bkg = tid >> 6;
    int sg[4];
    #pragma unroll
    for (int i = 0; i < 4; i++) sg[i] = slots[arA + i*32];

    #pragma unroll
    for (int i = 0; i < 4; i++)
        aR[i] = (sg[i] >= 0) ? *(const float4*)&xm[(long long)(sg[i] >> 1)*1024 + aqk] : make_float4(0,0,0,0);
    #pragma unroll
    for (int j = 0; j < 8; j++)
        bf[j] = Be[(long long)(bkg*8 + j) * 4096 + n0 + bnc];

    for (int k0 = 0; k0 < 1024; k0 += 32) {
        #pragma unroll
        for (int i = 0; i < 4; i++) {
            int base = (arA + i*32)*ASTR + (aqk >> 1);
            uint2 p0 = bfsplit2(aR[i].x, aR[i].y);
            uint2 p1 = bfsplit2(aR[i].z, aR[i].w);
            *(uint2*)&AsH[base] = make_uint2(p0.x, p1.x);
            *(uint2*)&AsL[base] = make_uint2(p0.y, p1.y);
        }
        {
            uint2 q0 = bfsplit2(bf[0], bf[1]);
            uint2 q1 = bfsplit2(bf[2], bf[3]);
            uint2 q2 = bfsplit2(bf[4], bf[5]);
            uint2 q3 = bfsplit2(bf[6], bf[7]);
            int base = bnc*ASTR + bkg*4;
            *(uint4*)&BsH[base] = make_uint4(q0.x, q1.x, q2.x, q3.x);
            *(uint4*)&BsL[base] = make_uint4(q0.y, q1.y, q2.y, q3.y);
        }
        __syncthreads();
        int k1 = k0 + 32;
        if (k1 < 1024) {
            #pragma unroll
            for (int i = 0; i < 4; i++)
                aR[i] = (sg[i] >= 0) ? *(const float4*)&xm[(long long)(sg[i] >> 1)*1024 + k1 + aqk] : make_float4(0,0,0,0);
            #pragma unroll
            for (int j = 0; j < 8; j++)
                bf[j] = Be[(long long)(k1 + bkg*8 + j) * 4096 + n0 + bnc];
        }
        mma_step_ldsm(c, AsH, AsL, BsH, BsL, aoff, boff, 0);
        mma_step_ldsm(c, AsH, AsL, BsH, BsL, aoff, boff, 8);
        __syncthreads();
    }

    #pragma unroll
    for (int mt = 0; mt < 2; mt++) {
        int lr0 = wm + mt*16 + g;
        int s0 = slots[lr0], s1 = slots[lr0 + 8];
        #pragma unroll
        for (int nt = 0; nt < 4; nt++) {
            int col = n0 + wn + nt*8 + tig*2;
            float bv0 = b1[e*4096 + col], bv1 = b1[e*4096 + col + 1];
            if (s0 >= 0) {
                float v0 = c[mt][nt][0] + bv0;
                float v1 = c[mt][nt][1] + bv1;
                v0 = 0.5f * v0 * (1.0f + erff(v0 * 0.70710677f));
                v1 = 0.5f * v1 * (1.0f + erff(v1 * 0.70710677f));
                g_h[(long long)s0*4096 + col]     = v0;
                g_h[(long long)s0*4096 + col + 1] = v1;
            }
            if (s1 >= 0) {
                float v2 = c[mt][nt][2] + bv0;
                float v3 = c[mt][nt][3] + bv1;
                v2 = 0.5f * v2 * (1.0f + erff(v2 * 0.70710677f));
                v3 = 0.5f * v3 * (1.0f + erff(v3 * 0.70710677f));
                g_h[(long long)s1*4096 + col]     = v2;
                g_h[(long long)s1*4096 + col + 1] = v3;
            }
        }
    }
}

__global__ __launch_bounds__(256, 2) void moe_mma2(const float* __restrict__ w2,
                                                   const float* __restrict__ b2) {
    int e = blockIdx.z;
    int cnt = g_counts[e];
    int m0 = blockIdx.y * 128;
    if (m0 >= cnt) return;
    int n0 = blockIdx.x * 64;

    __shared__ int slots[128];
    __shared__ unsigned AsH[128*ASTR], AsL[128*ASTR];
    __shared__ unsigned BsH[64*ASTR],  BsL[64*ASTR];

    int tid = threadIdx.x, lane = tid & 31, warp = tid >> 5;
    int g = lane >> 2, tig = lane & 3;
    int wm = (warp & 3) * 32, wn = (warp >> 2) * 32;
    if (tid < 128) slots[tid] = (m0 + tid < cnt) ? g_elist[e * MAXTOK + m0 + tid] : -1;
    __syncthreads();

    int aoff = a_ldsm_off(wm, lane);
    int boff = b_ldsm_off(wn, lane);

    const float* Be = w2 + (long long)e * 4096 * 1024;
    float c[2][4][4] = {};
    float4 aR[4];
    float  bf[8];

    int arA = tid >> 3, aqk = (tid & 7) << 2;
    int bnc = tid & 63, bkg = tid >> 6;
    int sg[4];
    #pragma unroll
    for (int i = 0; i < 4; i++) sg[i] = slots[arA + i*32];

    #pragma unroll
    for (int i = 0; i < 4; i++)
        aR[i] = (sg[i] >= 0) ? *(const float4*)&g_h[(long long)sg[i]*4096 + aqk] : make_float4(0,0,0,0);
    #pragma unroll
    for (int j = 0; j < 8; j++)
        bf[j] = Be[(long long)(bkg*8 + j) * 1024 + n0 + bnc];

    for (int k0 = 0; k0 < 4096; k0 += 32) {
        #pragma unroll
        for (int i = 0; i < 4; i++) {
            int base = (arA + i*32)*ASTR + (aqk >> 1);
            uint2 p0 = bfsplit2(aR[i].x, aR[i].y);
            uint2 p1 = bfsplit2(aR[i].z, aR[i].w);
            *(uint2*)&AsH[base] = make_uint2(p0.x, p1.x);
            *(uint2*)&AsL[base] = make_uint2(p0.y, p1.y);
        }
        {
            uint2 q0 = bfsplit2(bf[0], bf[1]);
            uint2 q1 = bfsplit2(bf[2], bf[3]);
            uint2 q2 = bfsplit2(bf[4], bf[5]);
            uint2 q3 = bfsplit2(bf[6], bf[7]);
            int base = bnc*ASTR + bkg*4;
            *(uint4*)&BsH[base] = make_uint4(q0.x, q1.x, q2.x, q3.x);
            *(uint4*)&BsL[base] = make_uint4(q0.y, q1.y, q2.y, q3.y);
        }
        __syncthreads();
        int k1 = k0 + 32;
        if (k1 < 4096) {
            #pragma unroll
            for (int i = 0; i < 4; i++)
                aR[i] = (sg[i] >= 0) ? *(const float4*)&g_h[(long long)sg[i]*4096 + k1 + aqk] : make_float4(0,0,0,0);
            #pragma unroll
            for (int j = 0; j < 8; j++)
                bf[j] = Be[(long long)(k1 + bkg*8 + j) * 1024 + n0 + bnc];
        }
        mma_step_ldsm(c, AsH, AsL, BsH, BsL, aoff, boff, 0);
        mma_step_ldsm(c, AsH, AsL, BsH, BsL, aoff, boff, 8);
        __syncthreads();
    }

    #pragma unroll
    for (int mt = 0; mt < 2; mt++) {
        int lr0 = wm + mt*16 + g;
        int s0 = slots[lr0], s1 = slots[lr0 + 8];
        #pragma unroll
        for (int nt = 0; nt < 4; nt++) {
            int col = n0 + wn + nt*8 + tig*2;
            float bv0 = b2[e*1024 + col], bv1 = b2[e*1024 + col + 1];
            if (s0 >= 0) {
                g_eo[(long long)s0*1024 + col]     = c[mt][nt][0] + bv0;
                g_eo[(long long)s0*1024 + col + 1] = c[mt][nt][1] + bv1;
            }
            if (s1 >= 0) {
                g_eo[(long long)s1*1024 + col]     = c[mt][nt][2] + bv0;
                g_eo[(long long)s1*1024 + col + 1] = c[mt][nt][3] + bv1;
            }
        }
    }
}

__global__ void combine_k(const float* __restrict__ x, float* __restrict__ out) {
    int idx = blockIdx.x * 256 + threadIdx.x;
    int t = idx >> 10, d = idx & 1023;
    float v = x[idx];
    v += g_probs[2*t]     * g_eo[(long long)(2*t)     * 1024 + d];
    v += g_probs[2*t + 1] * g_eo[(long long)(2*t + 1) * 1024 + d];
    out[idx] = v;
}

// ---------------- launcher ----------------
extern "C" void kernel_launch(void* const* d_in, const int* in_sizes, int n_in,
                              void* d_out, int out_size) {
    const float* q        = (const float*)d_in[0];
    const float* kv       = (const float*)d_in[1];
    const float* ln_cq_g  = (const float*)d_in[2];
    const float* ln_cq_b  = (const float*)d_in[3];
    const float* ln_ckv_g = (const float*)d_in[4];
    const float* ln_ckv_b = (const float*)d_in[5];
    const float* ln_s_g   = (const float*)d_in[6];
    const float* ln_s_b   = (const float*)d_in[7];
    const float* ln_m_g   = (const float*)d_in[8];
    const float* ln_m_b   = (const float*)d_in[9];
    const float* ca_in_w  = (const float*)d_in[10];
    const float* ca_in_b  = (const float*)d_in[11];
    const float* ca_out_w = (const float*)d_in[12];
    const float* ca_out_b = (const float*)d_in[13];
    const float* sa_in_w  = (const float*)d_in[14];
    const float* sa_in_b  = (const float*)d_in[15];
    const float* sa_out_w = (const float*)d_in[16];
    const float* sa_out_b = (const float*)d_in[17];
    const float* moe_rw   = (const float*)d_in[18];
    const float* moe_rb   = (const float*)d_in[19];
    const float* moe_nw   = (const float*)d_in[20];
    const float* moe_nb   = (const float*)d_in[21];
    const float* moe_w1   = (const float*)d_in[22];
    const float* moe_b1   = (const float*)d_in[23];
    const float* moe_w2   = (const float*)d_in[24];
    const float* moe_b2   = (const float*)d_in[25];
    float* out = (float*)d_out;

    float *p_x, *p_ln1, *p_lnkv, *p_qp, *p_kvp, *p_scores, *p_ao;
    cudaGetSymbolAddress((void**)&p_x,      g_x);
    cudaGetSymbolAddress((void**)&p_ln1,    g_ln1);
    cudaGetSymbolAddress((void**)&p_lnkv,   g_lnkv);
    cudaGetSymbolAddress((void**)&p_qp,     g_qp);
    cudaGetSymbolAddress((void**)&p_kvp,    g_kvp);
    cudaGetSymbolAddress((void**)&p_scores, g_scores);
    cudaGetSymbolAddress((void**)&p_ao,     g_ao);

    const long long ZL = 0;

    // ===== Cross-attention =====
    ln_k<<<TQ, 256>>>(q,  p_ln1,  ln_cq_g,  ln_cq_b);
    ln_k<<<TKV, 256>>>(kv, p_lnkv, ln_ckv_g, ln_ckv_b);

    mma_gemm<true><<<dim3(16, 16, 1), 256>>>(p_ln1, 1024, ZL, ZL,
        ca_in_w, 1024, ZL, ZL, p_qp, 1024, ZL, ZL,
        TQ, 1024, 1024, 1, ca_in_b, 1.0f, nullptr);
    mma_gemm<true><<<dim3(32, 32, 1), 256>>>(p_lnkv, 1024, ZL, ZL,
        ca_in_w + 1024*1024, 1024, ZL, ZL, p_kvp, 2048, ZL, ZL,
        TKV, 2048, 1024, 1, ca_in_b + 1024, 1.0f, nullptr);
    mma_gemm<true><<<dim3(32, 8, 32), 256>>>(
        p_qp, 1024, (long long)NQv*1024, 64,
        p_kvp, 2048, (long long)NKVv*2048, 64,
        p_scores, 2048, (long long)Hv*NQv*NKVv, (long long)NQv*NKVv,
        1024, 2048, 64, 16, nullptr, 0.125f, nullptr);
    softmax_k<<<Bv*Hv*NQv, 256>>>(p_scores, 2048);
    mma_gemm<false><<<dim3(1, 8, 32), 256>>>(
        p_scores, 2048, (long long)Hv*NQv*NKVv, (long long)NQv*NKVv,
        p_kvp + 1024, 2048, (long long)NKVv*2048, 64,
        p_ao, 1024, (long long)NQv*1024, 64,
        1024, 64, 2048, 16, nullptr, 1.0f, nullptr);
    mma_gemm<true><<<dim3(16, 16, 1), 256>>>(p_ao, 1024, ZL, ZL,
        ca_out_w, 1024, ZL, ZL, p_x, 1024, ZL, ZL,
        TQ, 1024, 1024, 1, ca_out_b, 1.0f, q);

    // ===== Self-attention =====
    ln_k<<<TQ, 256>>>(p_x, p_ln1, ln_s_g, ln_s_b);
    mma_gemm<true><<<dim3(48, 16, 1), 256>>>(p_ln1, 1024, ZL, ZL,
        sa_in_w, 1024, ZL, ZL, p_kvp, 3072, ZL, ZL,
        TQ, 3072, 1024, 1, sa_in_b, 1.0f, nullptr);
    mma_gemm<true><<<dim3(16, 8, 32), 256>>>(
        p_kvp, 3072, (long long)NQv*3072, 64,
        p_kvp + 1024, 3072, (long long)NQv*3072, 64,
        p_scores, 1024, (long long)Hv*NQv*NQv, (long long)NQv*NQv,
        1024, 1024, 64, 16, nullptr, 0.125f, nullptr);
    softmax_k<<<Bv*Hv*NQv, 256>>>(p_scores, 1024);
    mma_gemm<false><<<dim3(1, 8, 32), 256>>>(
        p_scores, 1024, (long long)Hv*NQv*NQv, (long long)NQv*NQv,
        p_kvp + 2048, 3072, (long long)NQv*3072, 64,
        p_ao, 1024, (long long)NQv*1024, 64,
        1024, 64, 1024, 16, nullptr, 1.0f, nullptr);
    mma_gemm<true><<<dim3(16, 16, 1), 256>>>(p_ao, 1024, ZL, ZL,
        sa_out_w, 1024, ZL, ZL, p_x, 1024, ZL, ZL,
        TQ, 1024, 1024, 1, sa_out_b, 1.0f, p_x);

    // ===== MoE =====
    ln_k<<<TQ, 256>>>(p_x, p_ln1, ln_m_g, ln_m_b);
    zero_counts_k<<<1, 32>>>();
    router_k<<<TQ, 256>>>(p_ln1, moe_rw, moe_rb, moe_nw, moe_nb);
    moe_mma1<<<dim3(64, 16, 8), 256>>>(p_ln1, moe_w1, moe_b1);
    moe_mma2<<<dim3(16, 16, 8), 256>>>(moe_w2, moe_b2);
    combine_k<<<(TQ*Dv)/256, 256>>>(p_x, out);
}